// round 3
// baseline (speedup 1.0000x reference)
#include <cuda_runtime.h>
#include <cuda_bf16.h>
#include <cstdint>

#define SQ 2048
#define DM 1024
#define NH 16
#define MR 4096

static __device__ float g_q[MR*DM];
static __device__ float g_k[MR*DM];
static __device__ float g_v[MR*DM];
static __device__ float g_ao[MR*DM];

// ---------------- PTX helpers ----------------
__device__ __forceinline__ uint32_t s2u(const void* p) {
    uint32_t a;
    asm("{ .reg .u64 t; cvta.to.shared.u64 t, %1; cvt.u32.u64 %0, t; }" : "=r"(a) : "l"(p));
    return a;
}
__device__ __forceinline__ void mma16816(float* d, const uint32_t* a, const uint32_t* b) {
    asm volatile(
        "mma.sync.aligned.m16n8k16.row.col.f32.bf16.bf16.f32 "
        "{%0,%1,%2,%3}, {%4,%5,%6,%7}, {%8,%9}, {%0,%1,%2,%3};"
        : "+f"(d[0]), "+f"(d[1]), "+f"(d[2]), "+f"(d[3])
        : "r"(a[0]), "r"(a[1]), "r"(a[2]), "r"(a[3]), "r"(b[0]), "r"(b[1]));
}
__device__ __forceinline__ void ldsm4(uint32_t* r, uint32_t addr) {
    asm volatile("ldmatrix.sync.aligned.m8n8.x4.shared.b16 {%0,%1,%2,%3}, [%4];"
        : "=r"(r[0]), "=r"(r[1]), "=r"(r[2]), "=r"(r[3]) : "r"(addr));
}
__device__ __forceinline__ void ldsm4t(uint32_t* r, uint32_t addr) {
    asm volatile("ldmatrix.sync.aligned.m8n8.x4.trans.shared.b16 {%0,%1,%2,%3}, [%4];"
        : "=r"(r[0]), "=r"(r[1]), "=r"(r[2]), "=r"(r[3]) : "r"(addr));
}
__device__ __forceinline__ uint32_t pack2(__nv_bfloat16 a, __nv_bfloat16 b) {
    __nv_bfloat162 t = __halves2bfloat162(a, b);
    return *reinterpret_cast<uint32_t*>(&t);
}
// split fp32x4 -> bf16 hi pair-packed + lo pair-packed
__device__ __forceinline__ void split4(float4 v, uint2& h, uint2& l) {
    __nv_bfloat16 hx = __float2bfloat16(v.x), hy = __float2bfloat16(v.y);
    __nv_bfloat16 hz = __float2bfloat16(v.z), hw = __float2bfloat16(v.w);
    __nv_bfloat16 lx = __float2bfloat16(v.x - __bfloat162float(hx));
    __nv_bfloat16 ly = __float2bfloat16(v.y - __bfloat162float(hy));
    __nv_bfloat16 lz = __float2bfloat16(v.z - __bfloat162float(hz));
    __nv_bfloat16 lw = __float2bfloat16(v.w - __bfloat162float(hw));
    h.x = pack2(hx, hy); h.y = pack2(hz, hw);
    l.x = pack2(lx, ly); l.y = pack2(lz, lw);
}

// ---------------------------------------------------------------------------
// Tensor-core GEMM: C[4096x1024] = A @ W + bias, fp32 via bf16 3-term split.
// CTA tile 128x128, K-step 32, 8 warps (warp tile 32x64), mma.m16n8k16.
// WMODE1: W stacked [H][D][64] -> W(k,c) = W[(c>>6)][k][c&63]
// ---------------------------------------------------------------------------
#define AST 40    // As row stride (bf16 elems), conflict-free for ldmatrix
#define BST 136   // Bs row stride
template<int WMODE>
__global__ void __launch_bounds__(256, 2) gemm_tc(const float* __restrict__ A,
                                                  const float* __restrict__ W,
                                                  const float* __restrict__ bias,
                                                  float* __restrict__ C)
{
    __shared__ __nv_bfloat16 Ah[128 * AST], Al[128 * AST];
    __shared__ __nv_bfloat16 Bh[32 * BST],  Bl[32 * BST];

    const int tid = threadIdx.x;
    const int wid = tid >> 5, lane = tid & 31;
    const int m0 = blockIdx.y * 128, n0 = blockIdx.x * 128;
    const int wm = (wid & 3) * 32;
    const int wn = (wid >> 2) * 64;

    float acc[2][8][4];
#pragma unroll
    for (int i = 0; i < 2; i++)
#pragma unroll
        for (int j = 0; j < 8; j++)
#pragma unroll
            for (int k = 0; k < 4; k++) acc[i][j][k] = 0.f;

    // ldmatrix per-lane element offsets
    const int aOff = (wm + (lane & 15)) * AST + (lane >> 4) * 8;
    const int bOff = (lane & 15) * BST + wn + (lane >> 4) * 8;
    const uint32_t aB[3] = { s2u(Ah) + (uint32_t)aOff * 2,
                             s2u(Al) + (uint32_t)aOff * 2,
                             s2u(Ah) + (uint32_t)aOff * 2 };
    const uint32_t bB[3] = { s2u(Bh) + (uint32_t)bOff * 2,
                             s2u(Bh) + (uint32_t)bOff * 2,
                             s2u(Bl) + (uint32_t)bOff * 2 };

    for (int k0 = 0; k0 < DM; k0 += 32) {
        // prefetch globals into regs
        float4 av[4], bv[4];
#pragma unroll
        for (int t = 0; t < 4; t++) {
            int idx = tid + t * 256;
            int m = idx >> 3, kq = (idx & 7) * 4;
            av[t] = *(const float4*)&A[(size_t)(m0 + m) * DM + k0 + kq];
        }
#pragma unroll
        for (int t = 0; t < 4; t++) {
            int idx = tid + t * 256;
            int k = idx >> 5, n = (idx & 31) * 4;
            if (WMODE) {
                int c = n0 + n;
                bv[t] = *(const float4*)&W[((size_t)(c >> 6) * DM + k0 + k) * 64 + (c & 63)];
            } else {
                bv[t] = *(const float4*)&W[(size_t)(k0 + k) * DM + n0 + n];
            }
        }
        __syncthreads();   // previous compute done reading smem
#pragma unroll
        for (int t = 0; t < 4; t++) {
            int idx = tid + t * 256;
            int m = idx >> 3, kq = (idx & 7) * 4;
            uint2 h, l; split4(av[t], h, l);
            *(uint2*)&Ah[m * AST + kq] = h;
            *(uint2*)&Al[m * AST + kq] = l;
        }
#pragma unroll
        for (int t = 0; t < 4; t++) {
            int idx = tid + t * 256;
            int k = idx >> 5, n = (idx & 31) * 4;
            uint2 h, l; split4(bv[t], h, l);
            *(uint2*)&Bh[k * BST + n] = h;
            *(uint2*)&Bl[k * BST + n] = l;
        }
        __syncthreads();

#pragma unroll
        for (int sp = 0; sp < 3; sp++) {
#pragma unroll
            for (int k16 = 0; k16 < 32; k16 += 16) {
                uint32_t af[2][4], bf[4][4];
                ldsm4(af[0], aB[sp] + (uint32_t)k16 * 2);
                ldsm4(af[1], aB[sp] + (uint32_t)(16 * AST + k16) * 2);
#pragma unroll
                for (int p = 0; p < 4; p++)
                    ldsm4t(bf[p], bB[sp] + (uint32_t)(k16 * BST + p * 16) * 2);
#pragma unroll
                for (int mt = 0; mt < 2; mt++)
#pragma unroll
                    for (int p = 0; p < 4; p++) {
                        mma16816(acc[mt][2 * p],     af[mt], &bf[p][0]);
                        mma16816(acc[mt][2 * p + 1], af[mt], &bf[p][2]);
                    }
            }
        }
    }

    // epilogue: d0,d1 -> row r, cols c,c+1 ; d2,d3 -> row r+8
    const int rm = m0 + wm + (lane >> 2);
    const int cn = n0 + wn + (lane & 3) * 2;
#pragma unroll
    for (int mt = 0; mt < 2; mt++)
#pragma unroll
        for (int nt = 0; nt < 8; nt++) {
            int gn = cn + nt * 8;
            float b0 = bias[gn], b1 = bias[gn + 1];
            int r0 = rm + mt * 16;
            float2 v0 = { acc[mt][nt][0] + b0, acc[mt][nt][1] + b1 };
            float2 v1 = { acc[mt][nt][2] + b0, acc[mt][nt][3] + b1 };
            *(float2*)&C[(size_t)r0 * DM + gn]       = v0;
            *(float2*)&C[(size_t)(r0 + 8) * DM + gn] = v1;
        }
}

// ---------------------------------------------------------------------------
// Fused batch-softmax attention (unchanged SIMT version).
// attn0 = sigmoid(d), attn1 = 1 - sigmoid(d), d = dot([q0|q1],[k0|-k1])/8
// ---------------------------------------------------------------------------
__global__ __launch_bounds__(256) void attn64(const float* __restrict__ qb,
                                              const float* __restrict__ kb,
                                              const float* __restrict__ vb,
                                              float* __restrict__ out)
{
    extern __shared__ float sm[];
    float* sQ  = sm;
    float* sKV = sm + 128 * 68;
    float* sP  = sKV + 128 * 68;
    float* sPc = sP + 64 * 68;

    const int tid = threadIdx.x;
    const int s0 = blockIdx.x * 64;
    const int h  = blockIdx.y;
    const int ty = tid >> 4, tx = tid & 15;
    const int hoff = h * 64;

    for (int i = tid; i < 64 * 128; i += 256) {
        int kk = i & 127, s = i >> 7;
        int b = kk >> 6;
        sQ[kk * 68 + s] = qb[(b * SQ + s0 + s) * DM + hoff + (kk & 63)];
    }

    float acc[4][8];
#pragma unroll
    for (int r = 0; r < 4; r++)
#pragma unroll
        for (int c = 0; c < 8; c++) acc[r][c] = 0.f;

    for (int t0 = 0; t0 < SQ; t0 += 64) {
        __syncthreads();
        for (int i = tid; i < 64 * 128; i += 256) {
            int kk = i & 127, t = i >> 7;
            int b = kk >> 6;
            float val = kb[(b * SQ + t0 + t) * DM + hoff + (kk & 63)];
            sKV[kk * 68 + t] = b ? -val : val;
        }
        __syncthreads();

        float sc[4][4];
#pragma unroll
        for (int r = 0; r < 4; r++)
#pragma unroll
            for (int c = 0; c < 4; c++) sc[r][c] = 0.f;
#pragma unroll 8
        for (int kk = 0; kk < 128; kk++) {
            float4 a  = *(const float4*)&sQ [kk * 68 + ty * 4];
            float4 b4 = *(const float4*)&sKV[kk * 68 + tx * 4];
            float av[4] = {a.x, a.y, a.z, a.w};
            float bv4[4] = {b4.x, b4.y, b4.z, b4.w};
#pragma unroll
            for (int r = 0; r < 4; r++)
#pragma unroll
                for (int c = 0; c < 4; c++)
                    sc[r][c] += av[r] * bv4[c];
        }

#pragma unroll
        for (int c = 0; c < 4; c++)
#pragma unroll
            for (int r = 0; r < 4; r++) {
                float p = 1.f / (1.f + __expf(-0.125f * sc[r][c]));
                sP [(tx * 4 + c) * 68 + ty * 4 + r] = p;
                sPc[(tx * 4 + c) * 68 + ty * 4 + r] = 1.f - p;
            }
        __syncthreads();

        for (int i = tid; i < 64 * 128; i += 256) {
            int c = i & 127, t = i >> 7;
            int b = c >> 6;
            sKV[t * 132 + c] = vb[(b * SQ + t0 + t) * DM + hoff + (c & 63)];
        }
        __syncthreads();

        const float* Pb = (tx < 8) ? sP : sPc;
#pragma unroll 8
        for (int kk = 0; kk < 64; kk++) {
            float4 a  = *(const float4*)&Pb[kk * 68 + ty * 4];
            float4 b0 = *(const float4*)&sKV[kk * 132 + tx * 8];
            float4 b1 = *(const float4*)&sKV[kk * 132 + tx * 8 + 4];
            float av[4] = {a.x, a.y, a.z, a.w};
            float bv8[8] = {b0.x, b0.y, b0.z, b0.w, b1.x, b1.y, b1.z, b1.w};
#pragma unroll
            for (int r = 0; r < 4; r++)
#pragma unroll
                for (int c = 0; c < 8; c++)
                    acc[r][c] += av[r] * bv8[c];
        }
    }

    const int b  = tx >> 3;
    const int cb = (tx & 7) * 8;
#pragma unroll
    for (int r = 0; r < 4; r++) {
        float* dst = &out[(b * SQ + s0 + ty * 4 + r) * DM + hoff + cb];
        float4 o0 = {acc[r][0], acc[r][1], acc[r][2], acc[r][3]};
        float4 o1 = {acc[r][4], acc[r][5], acc[r][6], acc[r][7]};
        *(float4*)dst       = o0;
        *(float4*)(dst + 4) = o1;
    }
}

// ---------------------------------------------------------------------------
extern "C" void kernel_launch(void* const* d_in, const int* in_sizes, int n_in,
                              void* d_out, int out_size)
{
    const float* query = (const float*)d_in[0];
    const float* key   = (const float*)d_in[1];
    const float* value = (const float*)d_in[2];
    const float* Wq = (const float*)d_in[3];
    const float* bq = (const float*)d_in[4];
    const float* Wk = (const float*)d_in[5];
    const float* bk = (const float*)d_in[6];
    const float* Wv = (const float*)d_in[7];
    const float* bv = (const float*)d_in[8];
    const float* Wo = (const float*)d_in[9];
    const float* bo = (const float*)d_in[10];
    float* out = (float*)d_out;

    float *qp, *kp, *vp, *aop;
    cudaGetSymbolAddress((void**)&qp,  g_q);
    cudaGetSymbolAddress((void**)&kp,  g_k);
    cudaGetSymbolAddress((void**)&vp,  g_v);
    cudaGetSymbolAddress((void**)&aop, g_ao);

    const int ATTN_SMEM = (128 * 68 * 2 + 64 * 68 * 2) * 4;  // 104448 B
    cudaFuncSetAttribute(attn64, cudaFuncAttributeMaxDynamicSharedMemorySize,
                         ATTN_SMEM);

    dim3 blk(256);
    dim3 gg(DM / 128, MR / 128);   // (8, 32)

    gemm_tc<1><<<gg, blk>>>(query, Wq, bq, qp);
    gemm_tc<1><<<gg, blk>>>(key,   Wk, bk, kp);
    gemm_tc<1><<<gg, blk>>>(value, Wv, bv, vp);

    attn64<<<dim3(SQ / 64, NH), blk, ATTN_SMEM>>>(qp, kp, vp, aop);

    gemm_tc<0><<<gg, blk>>>(aop, Wo, bo, out);
}

// round 5
// speedup vs baseline: 3.3607x; 3.3607x over previous
#include <cuda_runtime.h>
#include <cuda_bf16.h>
#include <cstdint>

#define SQ 2048
#define DM 1024
#define NH 16
#define MR 4096

static __device__ float g_q[MR*DM];
static __device__ float g_k[MR*DM];
static __device__ float g_v[MR*DM];
static __device__ float g_ao[MR*DM];
// bf16 split buffers for attention
static __device__ __nv_bfloat16 g_qh[NH*SQ*128], g_ql[NH*SQ*128];
static __device__ __nv_bfloat16 g_vh[NH*SQ*128], g_vl[NH*SQ*128];
static __device__ __nv_bfloat16 g_kth[NH*128*SQ], g_ktl[NH*128*SQ];

// ---------------- PTX helpers ----------------
__device__ __forceinline__ uint32_t s2u(const void* p) {
    uint32_t a;
    asm("{ .reg .u64 t; cvta.to.shared.u64 t, %1; cvt.u32.u64 %0, t; }" : "=r"(a) : "l"(p));
    return a;
}
__device__ __forceinline__ void mma16816(float* d, const uint32_t* a, const uint32_t* b) {
    asm volatile(
        "mma.sync.aligned.m16n8k16.row.col.f32.bf16.bf16.f32 "
        "{%0,%1,%2,%3}, {%4,%5,%6,%7}, {%8,%9}, {%0,%1,%2,%3};"
        : "+f"(d[0]), "+f"(d[1]), "+f"(d[2]), "+f"(d[3])
        : "r"(a[0]), "r"(a[1]), "r"(a[2]), "r"(a[3]), "r"(b[0]), "r"(b[1]));
}
__device__ __forceinline__ void ldsm4(uint32_t* r, uint32_t addr) {
    asm volatile("ldmatrix.sync.aligned.m8n8.x4.shared.b16 {%0,%1,%2,%3}, [%4];"
        : "=r"(r[0]), "=r"(r[1]), "=r"(r[2]), "=r"(r[3]) : "r"(addr));
}
__device__ __forceinline__ void ldsm4t(uint32_t* r, uint32_t addr) {
    asm volatile("ldmatrix.sync.aligned.m8n8.x4.trans.shared.b16 {%0,%1,%2,%3}, [%4];"
        : "=r"(r[0]), "=r"(r[1]), "=r"(r[2]), "=r"(r[3]) : "r"(addr));
}
__device__ __forceinline__ void cpa16(uint32_t dst, const void* src) {
    asm volatile("cp.async.cg.shared.global [%0], [%1], 16;" :: "r"(dst), "l"(src));
}
__device__ __forceinline__ void cpwait() {
    asm volatile("cp.async.commit_group;\n\tcp.async.wait_group 0;" ::: "memory");
}
__device__ __forceinline__ uint32_t pack2(__nv_bfloat16 a, __nv_bfloat16 b) {
    __nv_bfloat162 t = __halves2bfloat162(a, b);
    return *reinterpret_cast<uint32_t*>(&t);
}
__device__ __forceinline__ void split4(float4 v, uint2& h, uint2& l) {
    __nv_bfloat16 hx = __float2bfloat16(v.x), hy = __float2bfloat16(v.y);
    __nv_bfloat16 hz = __float2bfloat16(v.z), hw = __float2bfloat16(v.w);
    __nv_bfloat16 lx = __float2bfloat16(v.x - __bfloat162float(hx));
    __nv_bfloat16 ly = __float2bfloat16(v.y - __bfloat162float(hy));
    __nv_bfloat16 lz = __float2bfloat16(v.z - __bfloat162float(hz));
    __nv_bfloat16 lw = __float2bfloat16(v.w - __bfloat162float(hw));
    h.x = pack2(hx, hy); h.y = pack2(hz, hw);
    l.x = pack2(lx, ly); l.y = pack2(lz, lw);
}
__device__ __forceinline__ uint32_t packsplit2(float a, float b, uint32_t& lo) {
    __nv_bfloat16 ah = __float2bfloat16(a), bh = __float2bfloat16(b);
    __nv_bfloat16 al = __float2bfloat16(a - __bfloat162float(ah));
    __nv_bfloat16 bl = __float2bfloat16(b - __bfloat162float(bh));
    lo = pack2(al, bl);
    return pack2(ah, bh);
}

// ---------------------------------------------------------------------------
// Dense GEMM: fp32 via bf16 3-term split, mma.m16n8k16 (validated R2/R3)
// ---------------------------------------------------------------------------
#define AST 40
#define BST 136
template<int WMODE>
__global__ void __launch_bounds__(256, 2) gemm_tc(const float* __restrict__ A,
                                                  const float* __restrict__ W,
                                                  const float* __restrict__ bias,
                                                  float* __restrict__ C)
{
    __shared__ __nv_bfloat16 Ah[128 * AST], Al[128 * AST];
    __shared__ __nv_bfloat16 Bh[32 * BST],  Bl[32 * BST];

    const int tid = threadIdx.x;
    const int wid = tid >> 5, lane = tid & 31;
    const int m0 = blockIdx.y * 128, n0 = blockIdx.x * 128;
    const int wm = (wid & 3) * 32;
    const int wn = (wid >> 2) * 64;

    float acc[2][8][4];
#pragma unroll
    for (int i = 0; i < 2; i++)
#pragma unroll
        for (int j = 0; j < 8; j++)
#pragma unroll
            for (int k = 0; k < 4; k++) acc[i][j][k] = 0.f;

    const int aOff = (wm + (lane & 15)) * AST + (lane >> 4) * 8;
    const int bOff = (lane & 15) * BST + wn + (lane >> 4) * 8;
    const uint32_t aB[3] = { s2u(Ah) + (uint32_t)aOff * 2,
                             s2u(Al) + (uint32_t)aOff * 2,
                             s2u(Ah) + (uint32_t)aOff * 2 };
    const uint32_t bB[3] = { s2u(Bh) + (uint32_t)bOff * 2,
                             s2u(Bh) + (uint32_t)bOff * 2,
                             s2u(Bl) + (uint32_t)bOff * 2 };

    for (int k0 = 0; k0 < DM; k0 += 32) {
        float4 av[4], bv[4];
#pragma unroll
        for (int t = 0; t < 4; t++) {
            int idx = tid + t * 256;
            int m = idx >> 3, kq = (idx & 7) * 4;
            av[t] = *(const float4*)&A[(size_t)(m0 + m) * DM + k0 + kq];
        }
#pragma unroll
        for (int t = 0; t < 4; t++) {
            int idx = tid + t * 256;
            int k = idx >> 5, n = (idx & 31) * 4;
            if (WMODE) {
                int c = n0 + n;
                bv[t] = *(const float4*)&W[((size_t)(c >> 6) * DM + k0 + k) * 64 + (c & 63)];
            } else {
                bv[t] = *(const float4*)&W[(size_t)(k0 + k) * DM + n0 + n];
            }
        }
        __syncthreads();
#pragma unroll
        for (int t = 0; t < 4; t++) {
            int idx = tid + t * 256;
            int m = idx >> 3, kq = (idx & 7) * 4;
            uint2 h, l; split4(av[t], h, l);
            *(uint2*)&Ah[m * AST + kq] = h;
            *(uint2*)&Al[m * AST + kq] = l;
        }
#pragma unroll
        for (int t = 0; t < 4; t++) {
            int idx = tid + t * 256;
            int k = idx >> 5, n = (idx & 31) * 4;
            uint2 h, l; split4(bv[t], h, l);
            *(uint2*)&Bh[k * BST + n] = h;
            *(uint2*)&Bl[k * BST + n] = l;
        }
        __syncthreads();

#pragma unroll
        for (int sp = 0; sp < 3; sp++) {
#pragma unroll
            for (int k16 = 0; k16 < 32; k16 += 16) {
                uint32_t af[2][4], bf[4][4];
                ldsm4(af[0], aB[sp] + (uint32_t)k16 * 2);
                ldsm4(af[1], aB[sp] + (uint32_t)(16 * AST + k16) * 2);
#pragma unroll
                for (int p = 0; p < 4; p++)
                    ldsm4t(bf[p], bB[sp] + (uint32_t)(k16 * BST + p * 16) * 2);
#pragma unroll
                for (int mt = 0; mt < 2; mt++)
#pragma unroll
                    for (int p = 0; p < 4; p++) {
                        mma16816(acc[mt][2 * p],     af[mt], &bf[p][0]);
                        mma16816(acc[mt][2 * p + 1], af[mt], &bf[p][2]);
                    }
            }
        }
    }

    const int rm = m0 + wm + (lane >> 2);
    const int cn = n0 + wn + (lane & 3) * 2;
#pragma unroll
    for (int mt = 0; mt < 2; mt++)
#pragma unroll
        for (int nt = 0; nt < 8; nt++) {
            int gn = cn + nt * 8;
            float b0 = bias[gn], b1 = bias[gn + 1];
            int r0 = rm + mt * 16;
            float2 v0 = { acc[mt][nt][0] + b0, acc[mt][nt][1] + b1 };
            float2 v1 = { acc[mt][nt][2] + b0, acc[mt][nt][3] + b1 };
            *(float2*)&C[(size_t)r0 * DM + gn]       = v0;
            *(float2*)&C[(size_t)(r0 + 8) * DM + gn] = v1;
        }
}

// ---------------------------------------------------------------------------
// Prep 1: q/v fp32 [b,S,1024] -> bf16 hi/lo [h][s][kk=128] (kk = [x0|x1])
// ---------------------------------------------------------------------------
__global__ __launch_bounds__(256) void qvprep(const float* __restrict__ in,
                                              __nv_bfloat16* __restrict__ oh,
                                              __nv_bfloat16* __restrict__ ol)
{
    int idx = blockIdx.x * 256 + threadIdx.x;
    int kkq = (idx & 31) * 4;
    int s = (idx >> 5) & 2047;
    int h = idx >> 16;
    int b = kkq >> 6;
    float4 v = *(const float4*)&in[(size_t)(b * SQ + s) * DM + h * 64 + (kkq & 63)];
    uint2 hh, ll; split4(v, hh, ll);
    size_t o = ((size_t)h * SQ + s) * 128 + kkq;
    *(uint2*)&oh[o] = hh;
    *(uint2*)&ol[o] = ll;
}

// ---------------------------------------------------------------------------
// Prep 2: K fp32 -> transposed/negated bf16 hi/lo [h][kk=128][t]
// ---------------------------------------------------------------------------
__global__ __launch_bounds__(256) void kprep(const float* __restrict__ in,
                                             __nv_bfloat16* __restrict__ oh,
                                             __nv_bfloat16* __restrict__ ol)
{
    __shared__ float st[32][133];
    const int tid = threadIdx.x;
    const int h = blockIdx.x >> 6;
    const int t0 = (blockIdx.x & 63) * 32;
#pragma unroll
    for (int k = 0; k < 4; k++) {
        int i4 = tid + k * 256;
        int t = i4 >> 5, c4 = (i4 & 31) * 4;
        int b = c4 >> 6;
        float4 v = *(const float4*)&in[(size_t)(b * SQ + t0 + t) * DM + h * 64 + (c4 & 63)];
        if (b) { v.x = -v.x; v.y = -v.y; v.z = -v.z; v.w = -v.w; }
        st[t][c4] = v.x; st[t][c4 + 1] = v.y; st[t][c4 + 2] = v.z; st[t][c4 + 3] = v.w;
    }
    __syncthreads();
    const int kk = tid >> 1;
    const int th = (tid & 1) * 16;
    __nv_bfloat16 hv[16], lv[16];
#pragma unroll
    for (int j = 0; j < 16; j++) {
        float x = st[th + j][kk];
        __nv_bfloat16 xh = __float2bfloat16(x);
        hv[j] = xh;
        lv[j] = __float2bfloat16(x - __bfloat162float(xh));
    }
    size_t o = ((size_t)h * 128 + kk) * SQ + t0 + th;
    *(uint4*)&oh[o]     = *(uint4*)&hv[0];
    *(uint4*)&oh[o + 8] = *(uint4*)&hv[8];
    *(uint4*)&ol[o]     = *(uint4*)&lv[0];
    *(uint4*)&ol[o + 8] = *(uint4*)&lv[8];
}

// ---------------------------------------------------------------------------
// Tensor-core fused attention. CTA = (64 s-rows, head).
// ---------------------------------------------------------------------------
#define O_QH  0
#define O_QL  8704
#define O_KVH 17408
#define O_KVL 26624
#define O_PH  35840
#define O_PL  40448
#define O_PCH 45056
#define O_PCL 49664
#define ATTN_SMEM 108544

__global__ void __launch_bounds__(256, 2) attn_tc(
    const __nv_bfloat16* __restrict__ qh, const __nv_bfloat16* __restrict__ ql,
    const __nv_bfloat16* __restrict__ kth, const __nv_bfloat16* __restrict__ ktl,
    const __nv_bfloat16* __restrict__ vh, const __nv_bfloat16* __restrict__ vl,
    float* __restrict__ out)
{
    extern __shared__ __nv_bfloat16 sm[];
    const uint32_t sb = s2u(sm);
    const int tid = threadIdx.x;
    const int wid = tid >> 5, lane = tid & 31;
    const int s0 = blockIdx.x * 64;
    const int h  = blockIdx.y;

    const int wm   = (wid & 3) * 16;
    const int wnt  = (wid >> 2) * 32;
    const int wnc  = (wid >> 2) * 64;

    const uint32_t aQ  = sb + ((wm + (lane & 15)) * 136 + (lane >> 4) * 8) * 2;
    const uint32_t bK  = sb + O_KVH * 2 + ((lane & 15) * 72 + wnt + (lane >> 4) * 8) * 2;
    const uint32_t bKl = sb + O_KVL * 2 + ((lane & 15) * 72 + wnt + (lane >> 4) * 8) * 2;
    const uint32_t aP  = sb + ((wm + (lane & 15)) * 72 + (lane >> 4) * 8) * 2;
    const uint32_t bV  = sb + O_KVH * 2 + ((lane & 15) * 136 + wnc + (lane >> 4) * 8) * 2;
    const uint32_t bVl = sb + O_KVL * 2 + ((lane & 15) * 136 + wnc + (lane >> 4) * 8) * 2;

    // prologue: async-load Q tiles (hi+lo): 2 arrays x 64 rows x 16 chunks
    {
        const __nv_bfloat16* srcs[2] = { qh, ql };
        const uint32_t dsts[2] = { sb + O_QH * 2, sb + O_QL * 2 };
#pragma unroll
        for (int k = 0; k < 8; k++) {
            int c = tid + k * 256;
            int arr = c >> 10, rem = c & 1023;
            int r = rem >> 4, j = rem & 15;              // FIXED: 64 rows x 16 chunks
            cpa16(dsts[arr] + (uint32_t)(r * 136 + j * 8) * 2,
                  srcs[arr] + ((size_t)h * SQ + s0 + r) * 128 + j * 8);
        }
    }

    float acc[8][4];
#pragma unroll
    for (int f = 0; f < 8; f++)
#pragma unroll
        for (int j = 0; j < 4; j++) acc[f][j] = 0.f;

    const uint32_t pcsel = (wid >> 2) ? (uint32_t)(O_PCH - O_PH) * 2 : 0u;

    for (int t0 = 0; t0 < SQ; t0 += 64) {
        if (t0) __syncthreads();
        // load K [128 kk][64 t] hi+lo: 2 arrays x 128 rows x 8 chunks
        {
#pragma unroll
            for (int k = 0; k < 8; k++) {
                int c = tid + k * 256;
                int arr = c >> 10, rem = c & 1023;
                int kk = rem >> 3, j = rem & 7;
                const __nv_bfloat16* src = (arr ? ktl : kth)
                    + ((size_t)h * 128 + kk) * SQ + t0 + j * 8;
                uint32_t dst = sb + (arr ? O_KVL : O_KVH) * 2
                    + (uint32_t)(kk * 72 + j * 8) * 2;
                cpa16(dst, src);
            }
        }
        cpwait();
        __syncthreads();

        // ---- score mma: 3 splits x 8 k16-steps ----
        float sc[4][4];
#pragma unroll
        for (int g = 0; g < 4; g++)
#pragma unroll
            for (int j = 0; j < 4; j++) sc[g][j] = 0.f;
        const uint32_t aBs[3] = { aQ, aQ + O_QL * 2, aQ };
        const uint32_t bBs[3] = { bK, bK, bKl };
#pragma unroll
        for (int sp = 0; sp < 3; sp++) {
#pragma unroll
            for (int ks = 0; ks < 8; ks++) {
                uint32_t af[4], bf[2][4];
                ldsm4(af, aBs[sp] + (uint32_t)(ks * 16) * 2);
#pragma unroll
                for (int p = 0; p < 2; p++)
                    ldsm4t(bf[p], bBs[sp] + (uint32_t)(ks * 16 * 72 + p * 16) * 2);
#pragma unroll
                for (int p = 0; p < 2; p++) {
                    mma16816(sc[2 * p],     af, &bf[p][0]);
                    mma16816(sc[2 * p + 1], af, &bf[p][2]);
                }
            }
        }

        // ---- sigmoid + split + write P, 1-P ----
        {
            int r0 = wm + (lane >> 2);
            int cb = wnt + (lane & 3) * 2;
#pragma unroll
            for (int g = 0; g < 4; g++) {
                float p0 = 1.f / (1.f + __expf(-0.125f * sc[g][0]));
                float p1 = 1.f / (1.f + __expf(-0.125f * sc[g][1]));
                float p2 = 1.f / (1.f + __expf(-0.125f * sc[g][2]));
                float p3 = 1.f / (1.f + __expf(-0.125f * sc[g][3]));
                uint32_t lo, hi;
                int i0 = r0 * 72 + cb + 8 * g;
                int i1 = (r0 + 8) * 72 + cb + 8 * g;
                hi = packsplit2(p0, p1, lo);
                *(uint32_t*)&sm[O_PH + i0] = hi;  *(uint32_t*)&sm[O_PL + i0] = lo;
                hi = packsplit2(p2, p3, lo);
                *(uint32_t*)&sm[O_PH + i1] = hi;  *(uint32_t*)&sm[O_PL + i1] = lo;
                hi = packsplit2(1.f - p0, 1.f - p1, lo);
                *(uint32_t*)&sm[O_PCH + i0] = hi; *(uint32_t*)&sm[O_PCL + i0] = lo;
                hi = packsplit2(1.f - p2, 1.f - p3, lo);
                *(uint32_t*)&sm[O_PCH + i1] = hi; *(uint32_t*)&sm[O_PCL + i1] = lo;
            }
        }
        __syncthreads();

        // load V [64 t][128 c] hi+lo: 2 arrays x 64 rows x 16 chunks
        {
#pragma unroll
            for (int k = 0; k < 8; k++) {
                int c = tid + k * 256;
                int arr = c >> 10, rem = c & 1023;
                int r = rem >> 4, j = rem & 15;
                const __nv_bfloat16* src = (arr ? vl : vh)
                    + ((size_t)h * SQ + t0 + r) * 128 + j * 8;
                uint32_t dst = sb + (arr ? O_KVL : O_KVH) * 2
                    + (uint32_t)(r * 136 + j * 8) * 2;
                cpa16(dst, src);
            }
        }
        cpwait();
        __syncthreads();

        // ---- PV mma: 3 splits x 4 k16-steps, n64 per warp ----
        const uint32_t aPs[3] = { aP + O_PH * 2 + pcsel,
                                  aP + O_PL * 2 + pcsel,
                                  aP + O_PH * 2 + pcsel };
        const uint32_t bVs[3] = { bV, bV, bVl };
#pragma unroll
        for (int sp = 0; sp < 3; sp++) {
#pragma unroll
            for (int ks = 0; ks < 4; ks++) {
                uint32_t af[4], bf[4][4];
                ldsm4(af, aPs[sp] + (uint32_t)(ks * 16) * 2);
#pragma unroll
                for (int p = 0; p < 4; p++)
                    ldsm4t(bf[p], bVs[sp] + (uint32_t)(ks * 16 * 136 + p * 16) * 2);
#pragma unroll
                for (int p = 0; p < 4; p++) {
                    mma16816(acc[2 * p],     af, &bf[p][0]);
                    mma16816(acc[2 * p + 1], af, &bf[p][2]);
                }
            }
        }
    }

    // epilogue
    {
        int r0 = s0 + wm + (lane >> 2);
#pragma unroll
        for (int f = 0; f < 8; f++) {
            int c = wnc + 8 * f + (lane & 3) * 2;
            int b = c >> 6;
            size_t o = ((size_t)b * SQ + r0) * DM + h * 64 + (c & 63);
            float2 v0 = { acc[f][0], acc[f][1] };
            float2 v1 = { acc[f][2], acc[f][3] };
            *(float2*)&out[o]           = v0;
            *(float2*)&out[o + 8 * DM]  = v1;
        }
    }
}

// ---------------------------------------------------------------------------
extern "C" void kernel_launch(void* const* d_in, const int* in_sizes, int n_in,
                              void* d_out, int out_size)
{
    const float* query = (const float*)d_in[0];
    const float* key   = (const float*)d_in[1];
    const float* value = (const float*)d_in[2];
    const float* Wq = (const float*)d_in[3];
    const float* bq = (const float*)d_in[4];
    const float* Wk = (const float*)d_in[5];
    const float* bk = (const float*)d_in[6];
    const float* Wv = (const float*)d_in[7];
    const float* bv = (const float*)d_in[8];
    const float* Wo = (const float*)d_in[9];
    const float* bo = (const float*)d_in[10];
    float* out = (float*)d_out;

    float *qp, *kp, *vp, *aop;
    cudaGetSymbolAddress((void**)&qp,  g_q);
    cudaGetSymbolAddress((void**)&kp,  g_k);
    cudaGetSymbolAddress((void**)&vp,  g_v);
    cudaGetSymbolAddress((void**)&aop, g_ao);
    __nv_bfloat16 *qhp, *qlp, *vhp, *vlp, *kthp, *ktlp;
    cudaGetSymbolAddress((void**)&qhp,  g_qh);
    cudaGetSymbolAddress((void**)&qlp,  g_ql);
    cudaGetSymbolAddress((void**)&vhp,  g_vh);
    cudaGetSymbolAddress((void**)&vlp,  g_vl);
    cudaGetSymbolAddress((void**)&kthp, g_kth);
    cudaGetSymbolAddress((void**)&ktlp, g_ktl);

    cudaFuncSetAttribute(attn_tc, cudaFuncAttributeMaxDynamicSharedMemorySize,
                         ATTN_SMEM);

    dim3 blk(256);
    dim3 gg(DM / 128, MR / 128);

    gemm_tc<1><<<gg, blk>>>(query, Wq, bq, qp);
    gemm_tc<1><<<gg, blk>>>(key,   Wk, bk, kp);
    gemm_tc<1><<<gg, blk>>>(value, Wv, bv, vp);

    qvprep<<<4096, blk>>>(qp, qhp, qlp);
    qvprep<<<4096, blk>>>(vp, vhp, vlp);
    kprep <<<1024, blk>>>(kp, kthp, ktlp);

    attn_tc<<<dim3(SQ / 64, NH), blk, ATTN_SMEM>>>(qhp, qlp, kthp, ktlp,
                                                   vhp, vlp, aop);

    gemm_tc<0><<<gg, blk>>>(aop, Wo, bo, out);
}

// round 6
// speedup vs baseline: 3.7766x; 1.1238x over previous
#include <cuda_runtime.h>
#include <cuda_bf16.h>
#include <cstdint>

#define SQ 2048
#define DM 1024
#define NH 16
#define MR 4096

static __device__ float g_q[MR*DM];
static __device__ float g_k[MR*DM];
static __device__ float g_v[MR*DM];
static __device__ float g_ao[MR*DM];
static __device__ float g_v1s[NH*64];
// bf16 split buffers for attention
static __device__ __nv_bfloat16 g_qh[NH*SQ*128], g_ql[NH*SQ*128];
static __device__ __nv_bfloat16 g_vh[NH*SQ*128], g_vl[NH*SQ*128];
static __device__ __nv_bfloat16 g_kth[NH*128*SQ], g_ktl[NH*128*SQ];

// ---------------- PTX helpers ----------------
__device__ __forceinline__ uint32_t s2u(const void* p) {
    uint32_t a;
    asm("{ .reg .u64 t; cvta.to.shared.u64 t, %1; cvt.u32.u64 %0, t; }" : "=r"(a) : "l"(p));
    return a;
}
__device__ __forceinline__ void mma16816(float* d, const uint32_t* a, const uint32_t* b) {
    asm volatile(
        "mma.sync.aligned.m16n8k16.row.col.f32.bf16.bf16.f32 "
        "{%0,%1,%2,%3}, {%4,%5,%6,%7}, {%8,%9}, {%0,%1,%2,%3};"
        : "+f"(d[0]), "+f"(d[1]), "+f"(d[2]), "+f"(d[3])
        : "r"(a[0]), "r"(a[1]), "r"(a[2]), "r"(a[3]), "r"(b[0]), "r"(b[1]));
}
__device__ __forceinline__ void ldsm4(uint32_t* r, uint32_t addr) {
    asm volatile("ldmatrix.sync.aligned.m8n8.x4.shared.b16 {%0,%1,%2,%3}, [%4];"
        : "=r"(r[0]), "=r"(r[1]), "=r"(r[2]), "=r"(r[3]) : "r"(addr));
}
__device__ __forceinline__ void ldsm4t(uint32_t* r, uint32_t addr) {
    asm volatile("ldmatrix.sync.aligned.m8n8.x4.trans.shared.b16 {%0,%1,%2,%3}, [%4];"
        : "=r"(r[0]), "=r"(r[1]), "=r"(r[2]), "=r"(r[3]) : "r"(addr));
}
__device__ __forceinline__ void cpa16(uint32_t dst, const void* src) {
    asm volatile("cp.async.cg.shared.global [%0], [%1], 16;" :: "r"(dst), "l"(src));
}
__device__ __forceinline__ void cpcommit() {
    asm volatile("cp.async.commit_group;" ::: "memory");
}
__device__ __forceinline__ void cpwait1() {
    asm volatile("cp.async.wait_group 1;" ::: "memory");
}
__device__ __forceinline__ void cpwait0() {
    asm volatile("cp.async.wait_group 0;" ::: "memory");
}
__device__ __forceinline__ uint32_t pack2(__nv_bfloat16 a, __nv_bfloat16 b) {
    __nv_bfloat162 t = __halves2bfloat162(a, b);
    return *reinterpret_cast<uint32_t*>(&t);
}
__device__ __forceinline__ void split4(float4 v, uint2& h, uint2& l) {
    __nv_bfloat16 hx = __float2bfloat16(v.x), hy = __float2bfloat16(v.y);
    __nv_bfloat16 hz = __float2bfloat16(v.z), hw = __float2bfloat16(v.w);
    __nv_bfloat16 lx = __float2bfloat16(v.x - __bfloat162float(hx));
    __nv_bfloat16 ly = __float2bfloat16(v.y - __bfloat162float(hy));
    __nv_bfloat16 lz = __float2bfloat16(v.z - __bfloat162float(hz));
    __nv_bfloat16 lw = __float2bfloat16(v.w - __bfloat162float(hw));
    h.x = pack2(hx, hy); h.y = pack2(hz, hw);
    l.x = pack2(lx, ly); l.y = pack2(lz, lw);
}
__device__ __forceinline__ uint32_t packsplit2(float a, float b, uint32_t& lo) {
    __nv_bfloat16 ah = __float2bfloat16(a), bh = __float2bfloat16(b);
    __nv_bfloat16 al = __float2bfloat16(a - __bfloat162float(ah));
    __nv_bfloat16 bl = __float2bfloat16(b - __bfloat162float(bh));
    lo = pack2(al, bl);
    return pack2(ah, bh);
}

// ---------------------------------------------------------------------------
// Dense GEMM: fp32 via bf16 3-term split, mma.m16n8k16 (validated R2/R5)
// ---------------------------------------------------------------------------
#define AST 40
#define BST 136
template<int WMODE>
__global__ void __launch_bounds__(256, 2) gemm_tc(const float* __restrict__ A,
                                                  const float* __restrict__ W,
                                                  const float* __restrict__ bias,
                                                  float* __restrict__ C)
{
    __shared__ __nv_bfloat16 Ah[128 * AST], Al[128 * AST];
    __shared__ __nv_bfloat16 Bh[32 * BST],  Bl[32 * BST];

    const int tid = threadIdx.x;
    const int wid = tid >> 5, lane = tid & 31;
    const int m0 = blockIdx.y * 128, n0 = blockIdx.x * 128;
    const int wm = (wid & 3) * 32;
    const int wn = (wid >> 2) * 64;

    float acc[2][8][4];
#pragma unroll
    for (int i = 0; i < 2; i++)
#pragma unroll
        for (int j = 0; j < 8; j++)
#pragma unroll
            for (int k = 0; k < 4; k++) acc[i][j][k] = 0.f;

    const int aOff = (wm + (lane & 15)) * AST + (lane >> 4) * 8;
    const int bOff = (lane & 15) * BST + wn + (lane >> 4) * 8;
    const uint32_t aB[3] = { s2u(Ah) + (uint32_t)aOff * 2,
                             s2u(Al) + (uint32_t)aOff * 2,
                             s2u(Ah) + (uint32_t)aOff * 2 };
    const uint32_t bB[3] = { s2u(Bh) + (uint32_t)bOff * 2,
                             s2u(Bh) + (uint32_t)bOff * 2,
                             s2u(Bl) + (uint32_t)bOff * 2 };

    for (int k0 = 0; k0 < DM; k0 += 32) {
        float4 av[4], bv[4];
#pragma unroll
        for (int t = 0; t < 4; t++) {
            int idx = tid + t * 256;
            int m = idx >> 3, kq = (idx & 7) * 4;
            av[t] = *(const float4*)&A[(size_t)(m0 + m) * DM + k0 + kq];
        }
#pragma unroll
        for (int t = 0; t < 4; t++) {
            int idx = tid + t * 256;
            int k = idx >> 5, n = (idx & 31) * 4;
            if (WMODE) {
                int c = n0 + n;
                bv[t] = *(const float4*)&W[((size_t)(c >> 6) * DM + k0 + k) * 64 + (c & 63)];
            } else {
                bv[t] = *(const float4*)&W[(size_t)(k0 + k) * DM + n0 + n];
            }
        }
        __syncthreads();
#pragma unroll
        for (int t = 0; t < 4; t++) {
            int idx = tid + t * 256;
            int m = idx >> 3, kq = (idx & 7) * 4;
            uint2 h, l; split4(av[t], h, l);
            *(uint2*)&Ah[m * AST + kq] = h;
            *(uint2*)&Al[m * AST + kq] = l;
        }
#pragma unroll
        for (int t = 0; t < 4; t++) {
            int idx = tid + t * 256;
            int k = idx >> 5, n = (idx & 31) * 4;
            uint2 h, l; split4(bv[t], h, l);
            *(uint2*)&Bh[k * BST + n] = h;
            *(uint2*)&Bl[k * BST + n] = l;
        }
        __syncthreads();

#pragma unroll
        for (int sp = 0; sp < 3; sp++) {
#pragma unroll
            for (int k16 = 0; k16 < 32; k16 += 16) {
                uint32_t af[2][4], bf[4][4];
                ldsm4(af[0], aB[sp] + (uint32_t)k16 * 2);
                ldsm4(af[1], aB[sp] + (uint32_t)(16 * AST + k16) * 2);
#pragma unroll
                for (int p = 0; p < 4; p++)
                    ldsm4t(bf[p], bB[sp] + (uint32_t)(k16 * BST + p * 16) * 2);
#pragma unroll
                for (int mt = 0; mt < 2; mt++)
#pragma unroll
                    for (int p = 0; p < 4; p++) {
                        mma16816(acc[mt][2 * p],     af[mt], &bf[p][0]);
                        mma16816(acc[mt][2 * p + 1], af[mt], &bf[p][2]);
                    }
            }
        }
    }

    const int rm = m0 + wm + (lane >> 2);
    const int cn = n0 + wn + (lane & 3) * 2;
#pragma unroll
    for (int mt = 0; mt < 2; mt++)
#pragma unroll
        for (int nt = 0; nt < 8; nt++) {
            int gn = cn + nt * 8;
            float b0 = bias[gn], b1 = bias[gn + 1];
            int r0 = rm + mt * 16;
            float2 v0 = { acc[mt][nt][0] + b0, acc[mt][nt][1] + b1 };
            float2 v1 = { acc[mt][nt][2] + b0, acc[mt][nt][3] + b1 };
            *(float2*)&C[(size_t)r0 * DM + gn]       = v0;
            *(float2*)&C[(size_t)(r0 + 8) * DM + gn] = v1;
        }
}

// ---------------------------------------------------------------------------
// Prep 1: q/v fp32 [b,S,1024] -> bf16 hi/lo [h][s][kk=128]
// ---------------------------------------------------------------------------
__global__ __launch_bounds__(256) void qvprep(const float* __restrict__ in,
                                              __nv_bfloat16* __restrict__ oh,
                                              __nv_bfloat16* __restrict__ ol)
{
    int idx = blockIdx.x * 256 + threadIdx.x;
    int kkq = (idx & 31) * 4;
    int s = (idx >> 5) & 2047;
    int h = idx >> 16;
    int b = kkq >> 6;
    float4 v = *(const float4*)&in[(size_t)(b * SQ + s) * DM + h * 64 + (kkq & 63)];
    uint2 hh, ll; split4(v, hh, ll);
    size_t o = ((size_t)h * SQ + s) * 128 + kkq;
    *(uint2*)&oh[o] = hh;
    *(uint2*)&ol[o] = ll;
}

// ---------------------------------------------------------------------------
// Prep 2: K fp32 -> transposed/negated bf16 hi/lo [h][kk=128][t]
// ---------------------------------------------------------------------------
__global__ __launch_bounds__(256) void kprep(const float* __restrict__ in,
                                             __nv_bfloat16* __restrict__ oh,
                                             __nv_bfloat16* __restrict__ ol)
{
    __shared__ float st[32][133];
    const int tid = threadIdx.x;
    const int h = blockIdx.x >> 6;
    const int t0 = (blockIdx.x & 63) * 32;
#pragma unroll
    for (int k = 0; k < 4; k++) {
        int i4 = tid + k * 256;
        int t = i4 >> 5, c4 = (i4 & 31) * 4;
        int b = c4 >> 6;
        float4 v = *(const float4*)&in[(size_t)(b * SQ + t0 + t) * DM + h * 64 + (c4 & 63)];
        if (b) { v.x = -v.x; v.y = -v.y; v.z = -v.z; v.w = -v.w; }
        st[t][c4] = v.x; st[t][c4 + 1] = v.y; st[t][c4 + 2] = v.z; st[t][c4 + 3] = v.w;
    }
    __syncthreads();
    const int kk = tid >> 1;
    const int th = (tid & 1) * 16;
    __nv_bfloat16 hv[16], lv[16];
#pragma unroll
    for (int j = 0; j < 16; j++) {
        float x = st[th + j][kk];
        __nv_bfloat16 xh = __float2bfloat16(x);
        hv[j] = xh;
        lv[j] = __float2bfloat16(x - __bfloat162float(xh));
    }
    size_t o = ((size_t)h * 128 + kk) * SQ + t0 + th;
    *(uint4*)&oh[o]     = *(uint4*)&hv[0];
    *(uint4*)&oh[o + 8] = *(uint4*)&hv[8];
    *(uint4*)&ol[o]     = *(uint4*)&lv[0];
    *(uint4*)&ol[o + 8] = *(uint4*)&lv[8];
}

// ---------------------------------------------------------------------------
// Prep 3: V1 column sums: o[h][c] = sum_t v(b=1, t, h*64+c)  (fp32)
// ---------------------------------------------------------------------------
__global__ __launch_bounds__(256) void v1sum(const float* __restrict__ v,
                                             float* __restrict__ o)
{
    __shared__ float red[4][64];
    int h = blockIdx.x;
    int c = threadIdx.x & 63, q = threadIdx.x >> 6;
    float s = 0.f;
    for (int t = q * 512; t < (q + 1) * 512; t++)
        s += v[(size_t)(SQ + t) * DM + h * 64 + c];
    red[q][c] = s;
    __syncthreads();
    if (threadIdx.x < 64)
        o[h * 64 + threadIdx.x] = red[0][threadIdx.x] + red[1][threadIdx.x]
                                + red[2][threadIdx.x] + red[3][threadIdx.x];
}

// ---------------------------------------------------------------------------
// Tensor-core fused attention v2: V1sum trick + pipelined K/V prefetch +
// Q-hi fragments in registers. CTA = (64 s-rows, head), 2 CTA/SM.
// smem (bf16 elems):
//   QL 0      [64][136]   Q-lo
//   KH 8704   [128][72]   K-hi (t-major rows kk)
//   KL 17920  [128][72]
//   VH 27136  [64][136]   V-hi (also Q-hi staging at prologue)
//   VL 35840  [64][136]
//   PH 44544  [64][72]    sigmoid(d) hi
//   PL 49152  [64][72]
// ---------------------------------------------------------------------------
#define O_QL  0
#define O_KH  8704
#define O_KL  17920
#define O_VH  27136
#define O_VL  35840
#define O_PH  44544
#define O_PL  49152
#define ATTN_SMEM (53760 * 2)

__global__ void __launch_bounds__(256, 2) attn_tc(
    const __nv_bfloat16* __restrict__ qh_g, const __nv_bfloat16* __restrict__ ql_g,
    const __nv_bfloat16* __restrict__ kth,  const __nv_bfloat16* __restrict__ ktl,
    const __nv_bfloat16* __restrict__ vh_g, const __nv_bfloat16* __restrict__ vl_g,
    const float* __restrict__ v1s,
    float* __restrict__ out)
{
    extern __shared__ __nv_bfloat16 sm[];
    const uint32_t sb = s2u(sm);
    const int tid = threadIdx.x;
    const int wid = tid >> 5, lane = tid & 31;
    const int s0 = blockIdx.x * 64;
    const int h  = blockIdx.y;

    const int wm  = (wid & 3) * 16;
    const int wnt = (wid >> 2) * 32;
    const int wnc = (wid >> 2) * 64;

    const uint32_t aQl = sb + O_QL * 2 + ((wm + (lane & 15)) * 136 + (lane >> 4) * 8) * 2;
    const uint32_t bKh = sb + O_KH * 2 + ((lane & 15) * 72 + wnt + (lane >> 4) * 8) * 2;
    const uint32_t bKl = sb + O_KL * 2 + ((lane & 15) * 72 + wnt + (lane >> 4) * 8) * 2;
    const uint32_t aPh = sb + O_PH * 2 + ((wm + (lane & 15)) * 72 + (lane >> 4) * 8) * 2;
    const uint32_t aPl = sb + O_PL * 2 + ((wm + (lane & 15)) * 72 + (lane >> 4) * 8) * 2;
    const uint32_t bVh = sb + O_VH * 2 + ((lane & 15) * 136 + wnc + (lane >> 4) * 8) * 2;
    const uint32_t bVl = sb + O_VL * 2 + ((lane & 15) * 136 + wnc + (lane >> 4) * 8) * 2;

    // decode for 64x16-chunk tiles (Q/V): c in [0,2048)
    // decode for K tiles: 128 rows x 8 chunks per array

    // ---- prologue ----
    // group 0: Q-hi -> VH staging, Q-lo -> QL
#pragma unroll
    for (int k = 0; k < 8; k++) {
        int c = tid + k * 256;
        int arr = c >> 10, rem = c & 1023;
        int r = rem >> 4, j = rem & 15;
        const __nv_bfloat16* src = (arr ? ql_g : qh_g)
            + ((size_t)h * SQ + s0 + r) * 128 + j * 8;
        uint32_t dst = sb + (arr ? O_QL : O_VH) * 2 + (uint32_t)(r * 136 + j * 8) * 2;
        cpa16(dst, src);
    }
    cpcommit();
    // group 1: K(0)
#pragma unroll
    for (int k = 0; k < 8; k++) {
        int c = tid + k * 256;
        int arr = c >> 10, rem = c & 1023;
        int kk = rem >> 3, j = rem & 7;
        const __nv_bfloat16* src = (arr ? ktl : kth) + ((size_t)h * 128 + kk) * SQ + j * 8;
        uint32_t dst = sb + (arr ? O_KL : O_KH) * 2 + (uint32_t)(kk * 72 + j * 8) * 2;
        cpa16(dst, src);
    }
    cpcommit();
    cpwait1();          // Q done (K0 may pend)
    __syncthreads();

    // load Q-hi fragments to registers from VH staging
    uint32_t qhf[8][4];
    {
        uint32_t aQh = sb + O_VH * 2 + ((wm + (lane & 15)) * 136 + (lane >> 4) * 8) * 2;
#pragma unroll
        for (int ks = 0; ks < 8; ks++)
            ldsm4(qhf[ks], aQh + (uint32_t)(ks * 16) * 2);
    }
    __syncthreads();     // staging free

    // group 2: V(0)
#pragma unroll
    for (int k = 0; k < 8; k++) {
        int c = tid + k * 256;
        int arr = c >> 10, rem = c & 1023;
        int r = rem >> 4, j = rem & 15;
        const __nv_bfloat16* src = (arr ? vl_g : vh_g)
            + ((size_t)h * SQ + r) * 128 + j * 8;
        uint32_t dst = sb + (arr ? O_VL : O_VH) * 2 + (uint32_t)(r * 136 + j * 8) * 2;
        cpa16(dst, src);
    }
    cpcommit();

    float acc[8][4];
#pragma unroll
    for (int f = 0; f < 8; f++)
#pragma unroll
        for (int j = 0; j < 4; j++) acc[f][j] = 0.f;

    for (int t0 = 0; t0 < SQ; t0 += 64) {
        cpwait1();       // K(i) landed (V(i) may pend)
        __syncthreads();

        // ---- score: per ks: Qh(reg)*Kh + Ql*Kh + Qh*Kl ----
        float sc[4][4];
#pragma unroll
        for (int g = 0; g < 4; g++)
#pragma unroll
            for (int j = 0; j < 4; j++) sc[g][j] = 0.f;
#pragma unroll
        for (int ks = 0; ks < 8; ks++) {
            uint32_t ql4[4], kh[2][4], kl[2][4];
            ldsm4(ql4, aQl + (uint32_t)(ks * 16) * 2);
#pragma unroll
            for (int p = 0; p < 2; p++) {
                ldsm4t(kh[p], bKh + (uint32_t)(ks * 16 * 72 + p * 16) * 2);
                ldsm4t(kl[p], bKl + (uint32_t)(ks * 16 * 72 + p * 16) * 2);
            }
#pragma unroll
            for (int p = 0; p < 2; p++) {
                mma16816(sc[2 * p],     qhf[ks], &kh[p][0]);
                mma16816(sc[2 * p + 1], qhf[ks], &kh[p][2]);
                mma16816(sc[2 * p],     ql4,     &kh[p][0]);
                mma16816(sc[2 * p + 1], ql4,     &kh[p][2]);
                mma16816(sc[2 * p],     qhf[ks], &kl[p][0]);
                mma16816(sc[2 * p + 1], qhf[ks], &kl[p][2]);
            }
        }

        // ---- sigmoid + split + write P (no complement; V1sum handles b=1) ----
        {
            int r0 = wm + (lane >> 2);
            int cb = wnt + (lane & 3) * 2;
#pragma unroll
            for (int g = 0; g < 4; g++) {
                float p0 = 1.f / (1.f + __expf(-0.125f * sc[g][0]));
                float p1 = 1.f / (1.f + __expf(-0.125f * sc[g][1]));
                float p2 = 1.f / (1.f + __expf(-0.125f * sc[g][2]));
                float p3 = 1.f / (1.f + __expf(-0.125f * sc[g][3]));
                uint32_t lo, hi;
                int i0 = r0 * 72 + cb + 8 * g;
                int i1 = (r0 + 8) * 72 + cb + 8 * g;
                hi = packsplit2(p0, p1, lo);
                *(uint32_t*)&sm[O_PH + i0] = hi;  *(uint32_t*)&sm[O_PL + i0] = lo;
                hi = packsplit2(p2, p3, lo);
                *(uint32_t*)&sm[O_PH + i1] = hi;  *(uint32_t*)&sm[O_PL + i1] = lo;
            }
        }
        __syncthreads();   // P visible; K consumed by all warps

        // prefetch K(i+1)
        if (t0 + 64 < SQ) {
#pragma unroll
            for (int k = 0; k < 8; k++) {
                int c = tid + k * 256;
                int arr = c >> 10, rem = c & 1023;
                int kk = rem >> 3, j = rem & 7;
                const __nv_bfloat16* src = (arr ? ktl : kth)
                    + ((size_t)h * 128 + kk) * SQ + (t0 + 64) + j * 8;
                uint32_t dst = sb + (arr ? O_KL : O_KH) * 2
                    + (uint32_t)(kk * 72 + j * 8) * 2;
                cpa16(dst, src);
            }
        }
        cpcommit();

        cpwait1();         // V(i) landed (K(i+1) may pend)
        __syncthreads();

        // ---- PV: per ks: Ph*Vh + Pl*Vh + Ph*Vl ----
#pragma unroll
        for (int ks = 0; ks < 4; ks++) {
            uint32_t ph4[4], pl4[4], vh4[4][4], vl4[4][4];
            ldsm4(ph4, aPh + (uint32_t)(ks * 16) * 2);
            ldsm4(pl4, aPl + (uint32_t)(ks * 16) * 2);
#pragma unroll
            for (int p = 0; p < 4; p++) {
                ldsm4t(vh4[p], bVh + (uint32_t)(ks * 16 * 136 + p * 16) * 2);
                ldsm4t(vl4[p], bVl + (uint32_t)(ks * 16 * 136 + p * 16) * 2);
            }
#pragma unroll
            for (int p = 0; p < 4; p++) {
                mma16816(acc[2 * p],     ph4, &vh4[p][0]);
                mma16816(acc[2 * p + 1], ph4, &vh4[p][2]);
                mma16816(acc[2 * p],     pl4, &vh4[p][0]);
                mma16816(acc[2 * p + 1], pl4, &vh4[p][2]);
                mma16816(acc[2 * p],     ph4, &vl4[p][0]);
                mma16816(acc[2 * p + 1], ph4, &vl4[p][2]);
            }
        }
        __syncthreads();   // V/P consumed by all warps

        // prefetch V(i+1)
        if (t0 + 64 < SQ) {
#pragma unroll
            for (int k = 0; k < 8; k++) {
                int c = tid + k * 256;
                int arr = c >> 10, rem = c & 1023;
                int r = rem >> 4, j = rem & 15;
                const __nv_bfloat16* src = (arr ? vl_g : vh_g)
                    + ((size_t)h * SQ + (t0 + 64) + r) * 128 + j * 8;
                uint32_t dst = sb + (arr ? O_VL : O_VH) * 2
                    + (uint32_t)(r * 136 + j * 8) * 2;
                cpa16(dst, src);
            }
        }
        cpcommit();
    }
    cpwait0();

    // ---- epilogue: b=0 -> acc ; b=1 -> V1sum - acc ----
    {
        int r0 = s0 + wm + (lane >> 2);
#pragma unroll
        for (int f = 0; f < 8; f++) {
            int c = wnc + 8 * f + (lane & 3) * 2;
            int b = c >> 6;
            size_t o = ((size_t)b * SQ + r0) * DM + h * 64 + (c & 63);
            float2 v0, v1;
            if (b) {
                float sA = v1s[h * 64 + (c & 63)];
                float sB = v1s[h * 64 + (c & 63) + 1];
                v0 = { sA - acc[f][0], sB - acc[f][1] };
                v1 = { sA - acc[f][2], sB - acc[f][3] };
            } else {
                v0 = { acc[f][0], acc[f][1] };
                v1 = { acc[f][2], acc[f][3] };
            }
            *(float2*)&out[o]          = v0;
            *(float2*)&out[o + 8 * DM] = v1;
        }
    }
}

// ---------------------------------------------------------------------------
extern "C" void kernel_launch(void* const* d_in, const int* in_sizes, int n_in,
                              void* d_out, int out_size)
{
    const float* query = (const float*)d_in[0];
    const float* key   = (const float*)d_in[1];
    const float* value = (const float*)d_in[2];
    const float* Wq = (const float*)d_in[3];
    const float* bq = (const float*)d_in[4];
    const float* Wk = (const float*)d_in[5];
    const float* bk = (const float*)d_in[6];
    const float* Wv = (const float*)d_in[7];
    const float* bv = (const float*)d_in[8];
    const float* Wo = (const float*)d_in[9];
    const float* bo = (const float*)d_in[10];
    float* out = (float*)d_out;

    float *qp, *kp, *vp, *aop, *v1sp;
    cudaGetSymbolAddress((void**)&qp,   g_q);
    cudaGetSymbolAddress((void**)&kp,   g_k);
    cudaGetSymbolAddress((void**)&vp,   g_v);
    cudaGetSymbolAddress((void**)&aop,  g_ao);
    cudaGetSymbolAddress((void**)&v1sp, g_v1s);
    __nv_bfloat16 *qhp, *qlp, *vhp, *vlp, *kthp, *ktlp;
    cudaGetSymbolAddress((void**)&qhp,  g_qh);
    cudaGetSymbolAddress((void**)&qlp,  g_ql);
    cudaGetSymbolAddress((void**)&vhp,  g_vh);
    cudaGetSymbolAddress((void**)&vlp,  g_vl);
    cudaGetSymbolAddress((void**)&kthp, g_kth);
    cudaGetSymbolAddress((void**)&ktlp, g_ktl);

    cudaFuncSetAttribute(attn_tc, cudaFuncAttributeMaxDynamicSharedMemorySize,
                         ATTN_SMEM);

    dim3 blk(256);
    dim3 gg(DM / 128, MR / 128);

    gemm_tc<1><<<gg, blk>>>(query, Wq, bq, qp);
    gemm_tc<1><<<gg, blk>>>(key,   Wk, bk, kp);
    gemm_tc<1><<<gg, blk>>>(value, Wv, bv, vp);

    qvprep<<<4096, blk>>>(qp, qhp, qlp);
    qvprep<<<4096, blk>>>(vp, vhp, vlp);
    kprep <<<1024, blk>>>(kp, kthp, ktlp);
    v1sum <<<NH,   blk>>>(vp, v1sp);

    attn_tc<<<dim3(SQ / 64, NH), blk, ATTN_SMEM>>>(qhp, qlp, kthp, ktlp,
                                                   vhp, vlp, v1sp, aop);

    gemm_tc<0><<<gg, blk>>>(aop, Wo, bo, out);
}

// round 7
// speedup vs baseline: 3.8071x; 1.0081x over previous
#include <cuda_runtime.h>
#include <cuda_bf16.h>
#include <cstdint>

#define SQ 2048
#define DM 1024
#define NH 16
#define MR 4096

// fp32 scratch (K path) 
static __device__ float g_k[MR*DM];
static __device__ float g_v1s[NH*64];
// bf16 split GEMM inputs
static __device__ __nv_bfloat16 g_qAh[MR*DM], g_qAl[MR*DM];
static __device__ __nv_bfloat16 g_kAh[MR*DM], g_kAl[MR*DM];
static __device__ __nv_bfloat16 g_vAh[MR*DM], g_vAl[MR*DM];
static __device__ __nv_bfloat16 g_wqh[DM*DM], g_wql[DM*DM];
static __device__ __nv_bfloat16 g_wkh[DM*DM], g_wkl[DM*DM];
static __device__ __nv_bfloat16 g_wvh[DM*DM], g_wvl[DM*DM];
static __device__ __nv_bfloat16 g_woh[DM*DM], g_wol[DM*DM];
// attention operand layouts
static __device__ __nv_bfloat16 g_qh[NH*SQ*128], g_ql[NH*SQ*128];
static __device__ __nv_bfloat16 g_vh[NH*SQ*128], g_vl[NH*SQ*128];
static __device__ __nv_bfloat16 g_kth[NH*128*SQ], g_ktl[NH*128*SQ];
// attention output, split for final GEMM
static __device__ __nv_bfloat16 g_aoh[MR*DM], g_aol[MR*DM];

// ---------------- PTX helpers ----------------
__device__ __forceinline__ uint32_t s2u(const void* p) {
    uint32_t a;
    asm("{ .reg .u64 t; cvta.to.shared.u64 t, %1; cvt.u32.u64 %0, t; }" : "=r"(a) : "l"(p));
    return a;
}
__device__ __forceinline__ void mma16816(float* d, const uint32_t* a, const uint32_t* b) {
    asm volatile(
        "mma.sync.aligned.m16n8k16.row.col.f32.bf16.bf16.f32 "
        "{%0,%1,%2,%3}, {%4,%5,%6,%7}, {%8,%9}, {%0,%1,%2,%3};"
        : "+f"(d[0]), "+f"(d[1]), "+f"(d[2]), "+f"(d[3])
        : "r"(a[0]), "r"(a[1]), "r"(a[2]), "r"(a[3]), "r"(b[0]), "r"(b[1]));
}
__device__ __forceinline__ void ldsm4(uint32_t* r, uint32_t addr) {
    asm volatile("ldmatrix.sync.aligned.m8n8.x4.shared.b16 {%0,%1,%2,%3}, [%4];"
        : "=r"(r[0]), "=r"(r[1]), "=r"(r[2]), "=r"(r[3]) : "r"(addr));
}
__device__ __forceinline__ void ldsm4t(uint32_t* r, uint32_t addr) {
    asm volatile("ldmatrix.sync.aligned.m8n8.x4.trans.shared.b16 {%0,%1,%2,%3}, [%4];"
        : "=r"(r[0]), "=r"(r[1]), "=r"(r[2]), "=r"(r[3]) : "r"(addr));
}
__device__ __forceinline__ void cpa16(uint32_t dst, const void* src) {
    asm volatile("cp.async.cg.shared.global [%0], [%1], 16;" :: "r"(dst), "l"(src));
}
__device__ __forceinline__ void cpcommit() {
    asm volatile("cp.async.commit_group;" ::: "memory");
}
__device__ __forceinline__ void cpwait1() {
    asm volatile("cp.async.wait_group 1;" ::: "memory");
}
__device__ __forceinline__ void cpwait0() {
    asm volatile("cp.async.wait_group 0;" ::: "memory");
}
__device__ __forceinline__ uint32_t pack2(__nv_bfloat16 a, __nv_bfloat16 b) {
    __nv_bfloat162 t = __halves2bfloat162(a, b);
    return *reinterpret_cast<uint32_t*>(&t);
}
__device__ __forceinline__ void split4(float4 v, uint2& h, uint2& l) {
    __nv_bfloat16 hx = __float2bfloat16(v.x), hy = __float2bfloat16(v.y);
    __nv_bfloat16 hz = __float2bfloat16(v.z), hw = __float2bfloat16(v.w);
    __nv_bfloat16 lx = __float2bfloat16(v.x - __bfloat162float(hx));
    __nv_bfloat16 ly = __float2bfloat16(v.y - __bfloat162float(hy));
    __nv_bfloat16 lz = __float2bfloat16(v.z - __bfloat162float(hz));
    __nv_bfloat16 lw = __float2bfloat16(v.w - __bfloat162float(hw));
    h.x = pack2(hx, hy); h.y = pack2(hz, hw);
    l.x = pack2(lx, ly); l.y = pack2(lz, lw);
}
__device__ __forceinline__ uint32_t packsplit2(float a, float b, uint32_t& lo) {
    __nv_bfloat16 ah = __float2bfloat16(a), bh = __float2bfloat16(b);
    __nv_bfloat16 al = __float2bfloat16(a - __bfloat162float(ah));
    __nv_bfloat16 bl = __float2bfloat16(b - __bfloat162float(bh));
    lo = pack2(al, bl);
    return pack2(ah, bh);
}

// ---------------------------------------------------------------------------
// Prep: split generic fp32 row-major [R][1024] -> bf16 hi/lo (same layout).
// grid = R (one block per row), 256 threads, 1 float4 each.
// ---------------------------------------------------------------------------
__global__ __launch_bounds__(256) void splitA(const float4* __restrict__ A,
                                              __nv_bfloat16* __restrict__ oh,
                                              __nv_bfloat16* __restrict__ ol)
{
    size_t i = (size_t)blockIdx.x * 256 + threadIdx.x;
    uint2 h, l; split4(A[i], h, l);
    *(uint2*)&oh[i * 4] = h;
    *(uint2*)&ol[i * 4] = l;
}

// Prep: stacked W [16][1024][64] -> W'[k][c] bf16 hi/lo, W'(k,c)=W[c>>6][k][c&63]
__global__ __launch_bounds__(256) void splitW1(const float* __restrict__ W,
                                               __nv_bfloat16* __restrict__ oh,
                                               __nv_bfloat16* __restrict__ ol)
{
    size_t i = (size_t)blockIdx.x * 256 + threadIdx.x;   // over 1024*256 f4s
    int k = (int)(i >> 8);
    int c4 = (int)(i & 255) * 4;
    float4 v = *(const float4*)&W[((size_t)(c4 >> 6) * DM + k) * 64 + (c4 & 63)];
    uint2 h, l; split4(v, h, l);
    size_t o = (size_t)k * DM + c4;
    *(uint2*)&oh[o] = h;
    *(uint2*)&ol[o] = l;
}

// ---------------------------------------------------------------------------
// Pure-bf16 3-term GEMM, cp.async 2-stage pipeline.
// C[4096x1024] = (Ah+Al) @ (Bh+Bl) + bias,  A [M][1024] hi/lo, B [K][N] hi/lo.
// EMODE 0: fp32 C.  EMODE 1: split bf16 out in attn qv-layout [h][s][128].
// ---------------------------------------------------------------------------
#define GA_ST 40
#define GB_ST 136
#define SA_SZ (128*GA_ST)     // 5120 elems / stage / array
#define SB_SZ (32*GB_ST)      // 4352
#define OFF_AH(s) ((s)*SA_SZ)
#define OFF_AL(s) (2*SA_SZ + (s)*SA_SZ)
#define OFF_BH(s) (4*SA_SZ + (s)*SB_SZ)
#define OFF_BL(s) (4*SA_SZ + 2*SB_SZ + (s)*SB_SZ)
#define GEMM_SMEM ((4*SA_SZ + 4*SB_SZ) * 2)   // 75776 B

template<int EMODE>
__global__ void __launch_bounds__(256, 2) gemm_bf(
    const __nv_bfloat16* __restrict__ Ah_g, const __nv_bfloat16* __restrict__ Al_g,
    const __nv_bfloat16* __restrict__ Bh_g, const __nv_bfloat16* __restrict__ Bl_g,
    const float* __restrict__ bias,
    float* __restrict__ C,
    __nv_bfloat16* __restrict__ Oh, __nv_bfloat16* __restrict__ Ol)
{
    extern __shared__ __nv_bfloat16 gsm[];
    const uint32_t sb = s2u(gsm);
    const int tid = threadIdx.x;
    const int wid = tid >> 5, lane = tid & 31;
    const int m0 = blockIdx.y * 128, n0 = blockIdx.x * 128;
    const int wm = (wid & 3) * 32;
    const int wn = (wid >> 2) * 64;

    float acc[2][8][4];
#pragma unroll
    for (int i = 0; i < 2; i++)
#pragma unroll
        for (int j = 0; j < 8; j++)
#pragma unroll
            for (int k = 0; k < 4; k++) acc[i][j][k] = 0.f;

    const int aOff = (wm + (lane & 15)) * GA_ST + (lane >> 4) * 8;
    const int bOff = (lane & 15) * GB_ST + wn + (lane >> 4) * 8;

    // stage loader: 8 cpa16 per thread
    auto loadStage = [&](int s, int k0) {
#pragma unroll
        for (int t = 0; t < 4; t++) {               // A: 1024 chunks
            int c = tid + t * 256;
            int arr = c >> 9, rem = c & 511;
            int m = rem >> 2, j = rem & 3;
            const __nv_bfloat16* src = (arr ? Al_g : Ah_g)
                + (size_t)(m0 + m) * DM + k0 + j * 8;
            uint32_t dst = sb + (uint32_t)((arr ? OFF_AL(s) : OFF_AH(s))
                + m * GA_ST + j * 8) * 2;
            cpa16(dst, src);
        }
#pragma unroll
        for (int t = 0; t < 4; t++) {               // B: 1024 chunks
            int c = tid + t * 256;
            int arr = c >> 9, rem = c & 511;
            int k = rem >> 4, j = rem & 15;
            const __nv_bfloat16* src = (arr ? Bl_g : Bh_g)
                + (size_t)(k0 + k) * DM + n0 + j * 8;
            uint32_t dst = sb + (uint32_t)((arr ? OFF_BL(s) : OFF_BH(s))
                + k * GB_ST + j * 8) * 2;
            cpa16(dst, src);
        }
    };

    loadStage(0, 0);
    cpcommit();

    for (int i = 0; i < 32; i++) {
        cpwait0();
        __syncthreads();              // stage i&1 visible; prev MMA done in all warps
        if (i + 1 < 32) {
            loadStage((i + 1) & 1, (i + 1) * 32);
            cpcommit();
        }
        const int s = i & 1;
        const uint32_t ahB = sb + (uint32_t)(OFF_AH(s) + aOff) * 2;
        const uint32_t alB = sb + (uint32_t)(OFF_AL(s) + aOff) * 2;
        const uint32_t bhB = sb + (uint32_t)(OFF_BH(s) + bOff) * 2;
        const uint32_t blB = sb + (uint32_t)(OFF_BL(s) + bOff) * 2;
#pragma unroll
        for (int k16 = 0; k16 < 32; k16 += 16) {
            uint32_t ah[2][4], al[2][4];
            ldsm4(ah[0], ahB + (uint32_t)k16 * 2);
            ldsm4(ah[1], ahB + (uint32_t)(16 * GA_ST + k16) * 2);
            ldsm4(al[0], alB + (uint32_t)k16 * 2);
            ldsm4(al[1], alB + (uint32_t)(16 * GA_ST + k16) * 2);
#pragma unroll
            for (int p = 0; p < 4; p++) {
                uint32_t bh4[4], bl4[4];
                ldsm4t(bh4, bhB + (uint32_t)(k16 * GB_ST + p * 16) * 2);
                ldsm4t(bl4, blB + (uint32_t)(k16 * GB_ST + p * 16) * 2);
#pragma unroll
                for (int mt = 0; mt < 2; mt++) {
                    mma16816(acc[mt][2 * p],     ah[mt], &bh4[0]);
                    mma16816(acc[mt][2 * p + 1], ah[mt], &bh4[2]);
                    mma16816(acc[mt][2 * p],     al[mt], &bh4[0]);
                    mma16816(acc[mt][2 * p + 1], al[mt], &bh4[2]);
                    mma16816(acc[mt][2 * p],     ah[mt], &bl4[0]);
                    mma16816(acc[mt][2 * p + 1], ah[mt], &bl4[2]);
                }
            }
        }
    }

    // epilogue
    const int rm = m0 + wm + (lane >> 2);
    const int cn = n0 + wn + (lane & 3) * 2;
#pragma unroll
    for (int mt = 0; mt < 2; mt++)
#pragma unroll
        for (int nt = 0; nt < 8; nt++) {
            int gn = cn + nt * 8;
            float b0 = bias[gn], b1 = bias[gn + 1];
            int r0 = rm + mt * 16;
            float v00 = acc[mt][nt][0] + b0, v01 = acc[mt][nt][1] + b1;
            float v10 = acc[mt][nt][2] + b0, v11 = acc[mt][nt][3] + b1;
            if (EMODE == 0) {
                float2 a = { v00, v01 }, b = { v10, v11 };
                *(float2*)&C[(size_t)r0 * DM + gn]       = a;
                *(float2*)&C[(size_t)(r0 + 8) * DM + gn] = b;
            } else {
                int h = gn >> 6;
#pragma unroll
                for (int rr = 0; rr < 2; rr++) {
                    int r = r0 + rr * 8;
                    int s = r & 2047, bb = r >> 11;
                    int kk = (bb << 6) + (gn & 63);
                    size_t o = ((size_t)h * SQ + s) * 128 + kk;
                    uint32_t lo, hi;
                    hi = packsplit2(rr ? v10 : v00, rr ? v11 : v01, lo);
                    *(uint32_t*)&Oh[o] = hi;
                    *(uint32_t*)&Ol[o] = lo;
                }
            }
        }
}

// ---------------------------------------------------------------------------
// Prep: K fp32 -> transposed/negated bf16 hi/lo [h][kk=128][t]
// ---------------------------------------------------------------------------
__global__ __launch_bounds__(256) void kprep(const float* __restrict__ in,
                                             __nv_bfloat16* __restrict__ oh,
                                             __nv_bfloat16* __restrict__ ol)
{
    __shared__ float st[32][133];
    const int tid = threadIdx.x;
    const int h = blockIdx.x >> 6;
    const int t0 = (blockIdx.x & 63) * 32;
#pragma unroll
    for (int k = 0; k < 4; k++) {
        int i4 = tid + k * 256;
        int t = i4 >> 5, c4 = (i4 & 31) * 4;
        int b = c4 >> 6;
        float4 v = *(const float4*)&in[(size_t)(b * SQ + t0 + t) * DM + h * 64 + (c4 & 63)];
        if (b) { v.x = -v.x; v.y = -v.y; v.z = -v.z; v.w = -v.w; }
        st[t][c4] = v.x; st[t][c4 + 1] = v.y; st[t][c4 + 2] = v.z; st[t][c4 + 3] = v.w;
    }
    __syncthreads();
    const int kk = tid >> 1;
    const int th = (tid & 1) * 16;
    __nv_bfloat16 hv[16], lv[16];
#pragma unroll
    for (int j = 0; j < 16; j++) {
        float x = st[th + j][kk];
        __nv_bfloat16 xh = __float2bfloat16(x);
        hv[j] = xh;
        lv[j] = __float2bfloat16(x - __bfloat162float(xh));
    }
    size_t o = ((size_t)h * 128 + kk) * SQ + t0 + th;
    *(uint4*)&oh[o]     = *(uint4*)&hv[0];
    *(uint4*)&oh[o + 8] = *(uint4*)&hv[8];
    *(uint4*)&ol[o]     = *(uint4*)&lv[0];
    *(uint4*)&ol[o + 8] = *(uint4*)&lv[8];
}

// ---------------------------------------------------------------------------
// Prep: V1 column sums from split V: o[h][c] = sum_t (vh+vl)[h][t][64+c]
// ---------------------------------------------------------------------------
__global__ __launch_bounds__(256) void v1sum(const __nv_bfloat16* __restrict__ vh,
                                             const __nv_bfloat16* __restrict__ vl,
                                             float* __restrict__ o)
{
    __shared__ float red[4][64];
    int h = blockIdx.x;
    int c = threadIdx.x & 63, q = threadIdx.x >> 6;
    float s = 0.f;
    for (int t = q * 512; t < (q + 1) * 512; t++) {
        size_t ix = ((size_t)h * SQ + t) * 128 + 64 + c;
        s += __bfloat162float(vh[ix]) + __bfloat162float(vl[ix]);
    }
    red[q][c] = s;
    __syncthreads();
    if (threadIdx.x < 64)
        o[h * 64 + threadIdx.x] = red[0][threadIdx.x] + red[1][threadIdx.x]
                                + red[2][threadIdx.x] + red[3][threadIdx.x];
}

// ---------------------------------------------------------------------------
// Tensor-core fused attention (R6 mainloop; epilogue emits bf16 hi/lo).
// ---------------------------------------------------------------------------
#define O_QL  0
#define O_KH  8704
#define O_KL  17920
#define O_VH  27136
#define O_VL  35840
#define O_PH  44544
#define O_PL  49152
#define ATTN_SMEM (53760 * 2)

__global__ void __launch_bounds__(256, 2) attn_tc(
    const __nv_bfloat16* __restrict__ qh_g, const __nv_bfloat16* __restrict__ ql_g,
    const __nv_bfloat16* __restrict__ kth,  const __nv_bfloat16* __restrict__ ktl,
    const __nv_bfloat16* __restrict__ vh_g, const __nv_bfloat16* __restrict__ vl_g,
    const float* __restrict__ v1s,
    __nv_bfloat16* __restrict__ aoh, __nv_bfloat16* __restrict__ aol)
{
    extern __shared__ __nv_bfloat16 sm[];
    const uint32_t sb = s2u(sm);
    const int tid = threadIdx.x;
    const int wid = tid >> 5, lane = tid & 31;
    const int s0 = blockIdx.x * 64;
    const int h  = blockIdx.y;

    const int wm  = (wid & 3) * 16;
    const int wnt = (wid >> 2) * 32;
    const int wnc = (wid >> 2) * 64;

    const uint32_t aQl = sb + O_QL * 2 + ((wm + (lane & 15)) * 136 + (lane >> 4) * 8) * 2;
    const uint32_t bKh = sb + O_KH * 2 + ((lane & 15) * 72 + wnt + (lane >> 4) * 8) * 2;
    const uint32_t bKl = sb + O_KL * 2 + ((lane & 15) * 72 + wnt + (lane >> 4) * 8) * 2;
    const uint32_t aPh = sb + O_PH * 2 + ((wm + (lane & 15)) * 72 + (lane >> 4) * 8) * 2;
    const uint32_t aPl = sb + O_PL * 2 + ((wm + (lane & 15)) * 72 + (lane >> 4) * 8) * 2;
    const uint32_t bVh = sb + O_VH * 2 + ((lane & 15) * 136 + wnc + (lane >> 4) * 8) * 2;
    const uint32_t bVl = sb + O_VL * 2 + ((lane & 15) * 136 + wnc + (lane >> 4) * 8) * 2;

    // group 0: Q-hi -> VH staging, Q-lo -> QL
#pragma unroll
    for (int k = 0; k < 8; k++) {
        int c = tid + k * 256;
        int arr = c >> 10, rem = c & 1023;
        int r = rem >> 4, j = rem & 15;
        const __nv_bfloat16* src = (arr ? ql_g : qh_g)
            + ((size_t)h * SQ + s0 + r) * 128 + j * 8;
        uint32_t dst = sb + (arr ? O_QL : O_VH) * 2 + (uint32_t)(r * 136 + j * 8) * 2;
        cpa16(dst, src);
    }
    cpcommit();
    // group 1: K(0)
#pragma unroll
    for (int k = 0; k < 8; k++) {
        int c = tid + k * 256;
        int arr = c >> 10, rem = c & 1023;
        int kk = rem >> 3, j = rem & 7;
        const __nv_bfloat16* src = (arr ? ktl : kth) + ((size_t)h * 128 + kk) * SQ + j * 8;
        uint32_t dst = sb + (arr ? O_KL : O_KH) * 2 + (uint32_t)(kk * 72 + j * 8) * 2;
        cpa16(dst, src);
    }
    cpcommit();
    cpwait1();
    __syncthreads();

    uint32_t qhf[8][4];
    {
        uint32_t aQh = sb + O_VH * 2 + ((wm + (lane & 15)) * 136 + (lane >> 4) * 8) * 2;
#pragma unroll
        for (int ks = 0; ks < 8; ks++)
            ldsm4(qhf[ks], aQh + (uint32_t)(ks * 16) * 2);
    }
    __syncthreads();

    // group 2: V(0)
#pragma unroll
    for (int k = 0; k < 8; k++) {
        int c = tid + k * 256;
        int arr = c >> 10, rem = c & 1023;
        int r = rem >> 4, j = rem & 15;
        const __nv_bfloat16* src = (arr ? vl_g : vh_g)
            + ((size_t)h * SQ + r) * 128 + j * 8;
        uint32_t dst = sb + (arr ? O_VL : O_VH) * 2 + (uint32_t)(r * 136 + j * 8) * 2;
        cpa16(dst, src);
    }
    cpcommit();

    float acc[8][4];
#pragma unroll
    for (int f = 0; f < 8; f++)
#pragma unroll
        for (int j = 0; j < 4; j++) acc[f][j] = 0.f;

    for (int t0 = 0; t0 < SQ; t0 += 64) {
        cpwait1();
        __syncthreads();

        float sc[4][4];
#pragma unroll
        for (int g = 0; g < 4; g++)
#pragma unroll
            for (int j = 0; j < 4; j++) sc[g][j] = 0.f;
#pragma unroll
        for (int ks = 0; ks < 8; ks++) {
            uint32_t ql4[4], kh[2][4], kl[2][4];
            ldsm4(ql4, aQl + (uint32_t)(ks * 16) * 2);
#pragma unroll
            for (int p = 0; p < 2; p++) {
                ldsm4t(kh[p], bKh + (uint32_t)(ks * 16 * 72 + p * 16) * 2);
                ldsm4t(kl[p], bKl + (uint32_t)(ks * 16 * 72 + p * 16) * 2);
            }
#pragma unroll
            for (int p = 0; p < 2; p++) {
                mma16816(sc[2 * p],     qhf[ks], &kh[p][0]);
                mma16816(sc[2 * p + 1], qhf[ks], &kh[p][2]);
                mma16816(sc[2 * p],     ql4,     &kh[p][0]);
                mma16816(sc[2 * p + 1], ql4,     &kh[p][2]);
                mma16816(sc[2 * p],     qhf[ks], &kl[p][0]);
                mma16816(sc[2 * p + 1], qhf[ks], &kl[p][2]);
            }
        }

        {
            int r0 = wm + (lane >> 2);
            int cb = wnt + (lane & 3) * 2;
#pragma unroll
            for (int g = 0; g < 4; g++) {
                float p0 = 1.f / (1.f + __expf(-0.125f * sc[g][0]));
                float p1 = 1.f / (1.f + __expf(-0.125f * sc[g][1]));
                float p2 = 1.f / (1.f + __expf(-0.125f * sc[g][2]));
                float p3 = 1.f / (1.f + __expf(-0.125f * sc[g][3]));
                uint32_t lo, hi;
                int i0 = r0 * 72 + cb + 8 * g;
                int i1 = (r0 + 8) * 72 + cb + 8 * g;
                hi = packsplit2(p0, p1, lo);
                *(uint32_t*)&sm[O_PH + i0] = hi;  *(uint32_t*)&sm[O_PL + i0] = lo;
                hi = packsplit2(p2, p3, lo);
                *(uint32_t*)&sm[O_PH + i1] = hi;  *(uint32_t*)&sm[O_PL + i1] = lo;
            }
        }
        __syncthreads();

        if (t0 + 64 < SQ) {
#pragma unroll
            for (int k = 0; k < 8; k++) {
                int c = tid + k * 256;
                int arr = c >> 10, rem = c & 1023;
                int kk = rem >> 3, j = rem & 7;
                const __nv_bfloat16* src = (arr ? ktl : kth)
                    + ((size_t)h * 128 + kk) * SQ + (t0 + 64) + j * 8;
                uint32_t dst = sb + (arr ? O_KL : O_KH) * 2
                    + (uint32_t)(kk * 72 + j * 8) * 2;
                cpa16(dst, src);
            }
        }
        cpcommit();

        cpwait1();
        __syncthreads();

#pragma unroll
        for (int ks = 0; ks < 4; ks++) {
            uint32_t ph4[4], pl4[4], vh4[4][4], vl4[4][4];
            ldsm4(ph4, aPh + (uint32_t)(ks * 16) * 2);
            ldsm4(pl4, aPl + (uint32_t)(ks * 16) * 2);
#pragma unroll
            for (int p = 0; p < 4; p++) {
                ldsm4t(vh4[p], bVh + (uint32_t)(ks * 16 * 136 + p * 16) * 2);
                ldsm4t(vl4[p], bVl + (uint32_t)(ks * 16 * 136 + p * 16) * 2);
            }
#pragma unroll
            for (int p = 0; p < 4; p++) {
                mma16816(acc[2 * p],     ph4, &vh4[p][0]);
                mma16816(acc[2 * p + 1], ph4, &vh4[p][2]);
                mma16816(acc[2 * p],     pl4, &vh4[p][0]);
                mma16816(acc[2 * p + 1], pl4, &vh4[p][2]);
                mma16816(acc[2 * p],     ph4, &vl4[p][0]);
                mma16816(acc[2 * p + 1], ph4, &vl4[p][2]);
            }
        }
        __syncthreads();

        if (t0 + 64 < SQ) {
#pragma unroll
            for (int k = 0; k < 8; k++) {
                int c = tid + k * 256;
                int arr = c >> 10, rem = c & 1023;
                int r = rem >> 4, j = rem & 15;
                const __nv_bfloat16* src = (arr ? vl_g : vh_g)
                    + ((size_t)h * SQ + (t0 + 64) + r) * 128 + j * 8;
                uint32_t dst = sb + (arr ? O_VL : O_VH) * 2
                    + (uint32_t)(r * 136 + j * 8) * 2;
                cpa16(dst, src);
            }
        }
        cpcommit();
    }
    cpwait0();

    // epilogue: split-write for the final GEMM
    {
        int r0 = s0 + wm + (lane >> 2);
#pragma unroll
        for (int f = 0; f < 8; f++) {
            int c = wnc + 8 * f + (lane & 3) * 2;
            int b = c >> 6;
            size_t o = ((size_t)b * SQ + r0) * DM + h * 64 + (c & 63);
            float v00, v01, v10, v11;
            if (b) {
                float sA = v1s[h * 64 + (c & 63)];
                float sB = v1s[h * 64 + (c & 63) + 1];
                v00 = sA - acc[f][0]; v01 = sB - acc[f][1];
                v10 = sA - acc[f][2]; v11 = sB - acc[f][3];
            } else {
                v00 = acc[f][0]; v01 = acc[f][1];
                v10 = acc[f][2]; v11 = acc[f][3];
            }
            uint32_t lo, hi;
            hi = packsplit2(v00, v01, lo);
            *(uint32_t*)&aoh[o] = hi; *(uint32_t*)&aol[o] = lo;
            hi = packsplit2(v10, v11, lo);
            *(uint32_t*)&aoh[o + 8 * DM] = hi; *(uint32_t*)&aol[o + 8 * DM] = lo;
        }
    }
}

// ---------------------------------------------------------------------------
extern "C" void kernel_launch(void* const* d_in, const int* in_sizes, int n_in,
                              void* d_out, int out_size)
{
    const float* query = (const float*)d_in[0];
    const float* key   = (const float*)d_in[1];
    const float* value = (const float*)d_in[2];
    const float* Wq = (const float*)d_in[3];
    const float* bq = (const float*)d_in[4];
    const float* Wk = (const float*)d_in[5];
    const float* bk = (const float*)d_in[6];
    const float* Wv = (const float*)d_in[7];
    const float* bv = (const float*)d_in[8];
    const float* Wo = (const float*)d_in[9];
    const float* bo = (const float*)d_in[10];
    float* out = (float*)d_out;

    float *kp, *v1sp;
    cudaGetSymbolAddress((void**)&kp,   g_k);
    cudaGetSymbolAddress((void**)&v1sp, g_v1s);
    __nv_bfloat16 *qAh,*qAl,*kAh,*kAl,*vAh,*vAl;
    __nv_bfloat16 *wqh,*wql,*wkh,*wkl,*wvh,*wvl,*woh,*wol;
    __nv_bfloat16 *qhp,*qlp,*vhp,*vlp,*kthp,*ktlp,*aohp,*aolp;
    cudaGetSymbolAddress((void**)&qAh, g_qAh); cudaGetSymbolAddress((void**)&qAl, g_qAl);
    cudaGetSymbolAddress((void**)&kAh, g_kAh); cudaGetSymbolAddress((void**)&kAl, g_kAl);
    cudaGetSymbolAddress((void**)&vAh, g_vAh); cudaGetSymbolAddress((void**)&vAl, g_vAl);
    cudaGetSymbolAddress((void**)&wqh, g_wqh); cudaGetSymbolAddress((void**)&wql, g_wql);
    cudaGetSymbolAddress((void**)&wkh, g_wkh); cudaGetSymbolAddress((void**)&wkl, g_wkl);
    cudaGetSymbolAddress((void**)&wvh, g_wvh); cudaGetSymbolAddress((void**)&wvl, g_wvl);
    cudaGetSymbolAddress((void**)&woh, g_woh); cudaGetSymbolAddress((void**)&wol, g_wol);
    cudaGetSymbolAddress((void**)&qhp, g_qh);  cudaGetSymbolAddress((void**)&qlp, g_ql);
    cudaGetSymbolAddress((void**)&vhp, g_vh);  cudaGetSymbolAddress((void**)&vlp, g_vl);
    cudaGetSymbolAddress((void**)&kthp, g_kth); cudaGetSymbolAddress((void**)&ktlp, g_ktl);
    cudaGetSymbolAddress((void**)&aohp, g_aoh); cudaGetSymbolAddress((void**)&aolp, g_aol);

    cudaFuncSetAttribute(attn_tc, cudaFuncAttributeMaxDynamicSharedMemorySize,
                         ATTN_SMEM);
    cudaFuncSetAttribute(gemm_bf<0>, cudaFuncAttributeMaxDynamicSharedMemorySize,
                         GEMM_SMEM);
    cudaFuncSetAttribute(gemm_bf<1>, cudaFuncAttributeMaxDynamicSharedMemorySize,
                         GEMM_SMEM);

    dim3 blk(256);
    dim3 gg(DM / 128, MR / 128);   // (8, 32) = 256 CTAs, single wave

    // input splits
    splitA<<<MR, blk>>>((const float4*)query, qAh, qAl);
    splitA<<<MR, blk>>>((const float4*)key,   kAh, kAl);
    splitA<<<MR, blk>>>((const float4*)value, vAh, vAl);
    splitW1<<<DM, blk>>>(Wq, wqh, wql);
    splitW1<<<DM, blk>>>(Wk, wkh, wkl);
    splitW1<<<DM, blk>>>(Wv, wvh, wvl);
    splitA<<<DM, blk>>>((const float4*)Wo, woh, wol);

    // projections
    gemm_bf<1><<<gg, blk, GEMM_SMEM>>>(qAh, qAl, wqh, wql, bq, nullptr, qhp, qlp);
    gemm_bf<0><<<gg, blk, GEMM_SMEM>>>(kAh, kAl, wkh, wkl, bk, kp, nullptr, nullptr);
    gemm_bf<1><<<gg, blk, GEMM_SMEM>>>(vAh, vAl, wvh, wvl, bv, nullptr, vhp, vlp);

    kprep<<<1024, blk>>>(kp, kthp, ktlp);
    v1sum<<<NH, blk>>>(vhp, vlp, v1sp);

    attn_tc<<<dim3(SQ / 64, NH), blk, ATTN_SMEM>>>(qhp, qlp, kthp, ktlp,
                                                   vhp, vlp, v1sp, aohp, aolp);

    gemm_bf<0><<<gg, blk, GEMM_SMEM>>>(aohp, aolp, woh, wol, bo, out, nullptr, nullptr);
}

// round 9
// speedup vs baseline: 5.3714x; 1.4109x over previous
#include <cuda_runtime.h>
#include <cuda_fp16.h>
#include <cstdint>

#define SQ 2048
#define DM 1024
#define NH 16
#define MR 4096

static __device__ float g_k[MR*DM];
static __device__ float g_v1s[NH*64];
// fp16 split activations (A side), single-fp16 weights (B side)
static __device__ __half g_qAh[MR*DM], g_qAl[MR*DM];
static __device__ __half g_kAh[MR*DM], g_kAl[MR*DM];
static __device__ __half g_vAh[MR*DM], g_vAl[MR*DM];
static __device__ __half g_wq[DM*DM], g_wk[DM*DM], g_wv[DM*DM], g_wo[DM*DM];
// attention operands
static __device__ __half g_qh[NH*SQ*128], g_ql[NH*SQ*128];
static __device__ __half g_vh[NH*SQ*128], g_vdummy[NH*SQ*128];
static __device__ __half g_kth[NH*128*SQ];
// attention output, split for final GEMM
static __device__ __half g_aoh[MR*DM], g_aol[MR*DM];

// ---------------- PTX helpers ----------------
__device__ __forceinline__ uint32_t s2u(const void* p) {
    uint32_t a;
    asm("{ .reg .u64 t; cvta.to.shared.u64 t, %1; cvt.u32.u64 %0, t; }" : "=r"(a) : "l"(p));
    return a;
}
__device__ __forceinline__ void mma16816(float* d, const uint32_t* a, const uint32_t* b) {
    asm volatile(
        "mma.sync.aligned.m16n8k16.row.col.f32.f16.f16.f32 "
        "{%0,%1,%2,%3}, {%4,%5,%6,%7}, {%8,%9}, {%0,%1,%2,%3};"
        : "+f"(d[0]), "+f"(d[1]), "+f"(d[2]), "+f"(d[3])
        : "r"(a[0]), "r"(a[1]), "r"(a[2]), "r"(a[3]), "r"(b[0]), "r"(b[1]));
}
__device__ __forceinline__ void ldsm4(uint32_t* r, uint32_t addr) {
    asm volatile("ldmatrix.sync.aligned.m8n8.x4.shared.b16 {%0,%1,%2,%3}, [%4];"
        : "=r"(r[0]), "=r"(r[1]), "=r"(r[2]), "=r"(r[3]) : "r"(addr));
}
__device__ __forceinline__ void ldsm4t(uint32_t* r, uint32_t addr) {
    asm volatile("ldmatrix.sync.aligned.m8n8.x4.trans.shared.b16 {%0,%1,%2,%3}, [%4];"
        : "=r"(r[0]), "=r"(r[1]), "=r"(r[2]), "=r"(r[3]) : "r"(addr));
}
__device__ __forceinline__ void cpa16(uint32_t dst, const void* src) {
    asm volatile("cp.async.cg.shared.global [%0], [%1], 16;" :: "r"(dst), "l"(src));
}
__device__ __forceinline__ void cpcommit() {
    asm volatile("cp.async.commit_group;" ::: "memory");
}
__device__ __forceinline__ void cpwait1() {
    asm volatile("cp.async.wait_group 1;" ::: "memory");
}
__device__ __forceinline__ void cpwait0() {
    asm volatile("cp.async.wait_group 0;" ::: "memory");
}
__device__ __forceinline__ uint32_t pack2(__half a, __half b) {
    __half2 t = __halves2half2(a, b);
    return *reinterpret_cast<uint32_t*>(&t);
}
// split fp32x4 -> fp16 hi pair-packed + lo pair-packed
__device__ __forceinline__ void split4(float4 v, uint2& h, uint2& l) {
    __half hx = __float2half_rn(v.x), hy = __float2half_rn(v.y);
    __half hz = __float2half_rn(v.z), hw = __float2half_rn(v.w);
    __half lx = __float2half_rn(v.x - __half2float(hx));
    __half ly = __float2half_rn(v.y - __half2float(hy));
    __half lz = __float2half_rn(v.z - __half2float(hz));
    __half lw = __float2half_rn(v.w - __half2float(hw));
    h.x = pack2(hx, hy); h.y = pack2(hz, hw);
    l.x = pack2(lx, ly); l.y = pack2(lz, lw);
}
// fp32x4 -> fp16 single pair-packed
__device__ __forceinline__ uint2 round4(float4 v) {
    uint2 r;
    r.x = pack2(__float2half_rn(v.x), __float2half_rn(v.y));
    r.y = pack2(__float2half_rn(v.z), __float2half_rn(v.w));
    return r;
}
__device__ __forceinline__ uint32_t packsplit2(float a, float b, uint32_t& lo) {
    __half ah = __float2half_rn(a), bh = __float2half_rn(b);
    __half al = __float2half_rn(a - __half2float(ah));
    __half bl = __float2half_rn(b - __half2float(bh));
    lo = pack2(al, bl);
    return pack2(ah, bh);
}

// ---------------------------------------------------------------------------
// Prep: split fp32 row-major [R][1024] -> fp16 hi/lo (same layout)
// ---------------------------------------------------------------------------
__global__ __launch_bounds__(256) void splitA(const float4* __restrict__ A,
                                              __half* __restrict__ oh,
                                              __half* __restrict__ ol)
{
    size_t i = (size_t)blockIdx.x * 256 + threadIdx.x;
    uint2 h, l; split4(A[i], h, l);
    *(uint2*)&oh[i * 4] = h;
    *(uint2*)&ol[i * 4] = l;
}

// Prep: round fp32 [R][1024] -> single fp16 (Wo path)
__global__ __launch_bounds__(256) void roundA(const float4* __restrict__ A,
                                              __half* __restrict__ o)
{
    size_t i = (size_t)blockIdx.x * 256 + threadIdx.x;
    *(uint2*)&o[i * 4] = round4(A[i]);
}

// Prep: stacked W [16][1024][64] -> single fp16 W'[k][c], W'(k,c)=W[c>>6][k][c&63]
__global__ __launch_bounds__(256) void roundW1(const float* __restrict__ W,
                                               __half* __restrict__ o)
{
    size_t i = (size_t)blockIdx.x * 256 + threadIdx.x;   // over 1024*256 f4s
    int k = (int)(i >> 8);
    int c4 = (int)(i & 255) * 4;
    float4 v = *(const float4*)&W[((size_t)(c4 >> 6) * DM + k) * 64 + (c4 & 63)];
    *(uint2*)&o[(size_t)k * DM + c4] = round4(v);
}

// ---------------------------------------------------------------------------
// fp16 2-term GEMM, cp.async 2-stage pipeline.
// C[4096x1024] = (Ah+Al) @ B + bias,  A [M][1024] hi/lo fp16, B [K][N] fp16.
// EMODE 0: fp32 C.  EMODE 1: split fp16 out in attn layout [h][s][128].
// ---------------------------------------------------------------------------
#define GA_ST 40
#define GB_ST 136
#define SA_SZ (128*GA_ST)     // 5120 elems / stage / array
#define SB_SZ (32*GB_ST)      // 4352
#define OFF_AH(s) ((s)*SA_SZ)
#define OFF_AL(s) (2*SA_SZ + (s)*SA_SZ)
#define OFF_B(s)  (4*SA_SZ + (s)*SB_SZ)
#define GEMM_SMEM ((4*SA_SZ + 2*SB_SZ) * 2)   // 58368 B

template<int EMODE>
__global__ void __launch_bounds__(256, 2) gemm_hf(
    const __half* __restrict__ Ah_g, const __half* __restrict__ Al_g,
    const __half* __restrict__ B_g,
    const float* __restrict__ bias,
    float* __restrict__ C,
    __half* __restrict__ Oh, __half* __restrict__ Ol)
{
    extern __shared__ __half gsm[];
    const uint32_t sb = s2u(gsm);
    const int tid = threadIdx.x;
    const int wid = tid >> 5, lane = tid & 31;
    const int m0 = blockIdx.y * 128, n0 = blockIdx.x * 128;
    const int wm = (wid & 3) * 32;
    const int wn = (wid >> 2) * 64;

    float acc[2][8][4];
#pragma unroll
    for (int i = 0; i < 2; i++)
#pragma unroll
        for (int j = 0; j < 8; j++)
#pragma unroll
            for (int k = 0; k < 4; k++) acc[i][j][k] = 0.f;

    const int aOff = (wm + (lane & 15)) * GA_ST + (lane >> 4) * 8;
    const int bOff = (lane & 15) * GB_ST + wn + (lane >> 4) * 8;

    auto loadStage = [&](int s, int k0) {
#pragma unroll
        for (int t = 0; t < 4; t++) {               // A hi/lo: 1024 chunks
            int c = tid + t * 256;
            int arr = c >> 9, rem = c & 511;
            int m = rem >> 2, j = rem & 3;
            const __half* src = (arr ? Al_g : Ah_g)
                + (size_t)(m0 + m) * DM + k0 + j * 8;
            uint32_t dst = sb + (uint32_t)((arr ? OFF_AL(s) : OFF_AH(s))
                + m * GA_ST + j * 8) * 2;
            cpa16(dst, src);
        }
#pragma unroll
        for (int t = 0; t < 2; t++) {               // B: 512 chunks
            int c = tid + t * 256;
            int k = c >> 4, j = c & 15;
            const __half* src = B_g + (size_t)(k0 + k) * DM + n0 + j * 8;
            uint32_t dst = sb + (uint32_t)(OFF_B(s) + k * GB_ST + j * 8) * 2;
            cpa16(dst, src);
        }
    };

    loadStage(0, 0);
    cpcommit();

    for (int i = 0; i < 32; i++) {
        cpwait0();
        __syncthreads();
        if (i + 1 < 32) {
            loadStage((i + 1) & 1, (i + 1) * 32);
            cpcommit();
        }
        const int s = i & 1;
        const uint32_t ahB = sb + (uint32_t)(OFF_AH(s) + aOff) * 2;
        const uint32_t alB = sb + (uint32_t)(OFF_AL(s) + aOff) * 2;
        const uint32_t bB  = sb + (uint32_t)(OFF_B(s)  + bOff) * 2;
#pragma unroll
        for (int k16 = 0; k16 < 32; k16 += 16) {
            uint32_t ah[2][4], al[2][4];
            ldsm4(ah[0], ahB + (uint32_t)k16 * 2);
            ldsm4(ah[1], ahB + (uint32_t)(16 * GA_ST + k16) * 2);
            ldsm4(al[0], alB + (uint32_t)k16 * 2);
            ldsm4(al[1], alB + (uint32_t)(16 * GA_ST + k16) * 2);
#pragma unroll
            for (int p = 0; p < 4; p++) {
                uint32_t b4[4];
                ldsm4t(b4, bB + (uint32_t)(k16 * GB_ST + p * 16) * 2);
#pragma unroll
                for (int mt = 0; mt < 2; mt++) {
                    mma16816(acc[mt][2 * p],     ah[mt], &b4[0]);
                    mma16816(acc[mt][2 * p + 1], ah[mt], &b4[2]);
                    mma16816(acc[mt][2 * p],     al[mt], &b4[0]);
                    mma16816(acc[mt][2 * p + 1], al[mt], &b4[2]);
                }
            }
        }
    }

    const int rm = m0 + wm + (lane >> 2);
    const int cn = n0 + wn + (lane & 3) * 2;
#pragma unroll
    for (int mt = 0; mt < 2; mt++)
#pragma unroll
        for (int nt = 0; nt < 8; nt++) {
            int gn = cn + nt * 8;
            float b0 = bias[gn], b1 = bias[gn + 1];
            int r0 = rm + mt * 16;
            float v00 = acc[mt][nt][0] + b0, v01 = acc[mt][nt][1] + b1;
            float v10 = acc[mt][nt][2] + b0, v11 = acc[mt][nt][3] + b1;
            if (EMODE == 0) {
                float2 a = { v00, v01 }, b = { v10, v11 };
                *(float2*)&C[(size_t)r0 * DM + gn]       = a;
                *(float2*)&C[(size_t)(r0 + 8) * DM + gn] = b;
            } else {
                int h = gn >> 6;
#pragma unroll
                for (int rr = 0; rr < 2; rr++) {
                    int r = r0 + rr * 8;
                    int s = r & 2047, bb = r >> 11;
                    int kk = (bb << 6) + (gn & 63);
                    size_t o = ((size_t)h * SQ + s) * 128 + kk;
                    uint32_t lo, hi;
                    hi = packsplit2(rr ? v10 : v00, rr ? v11 : v01, lo);
                    *(uint32_t*)&Oh[o] = hi;
                    *(uint32_t*)&Ol[o] = lo;
                }
            }
        }
}

// ---------------------------------------------------------------------------
// Prep: K fp32 -> transposed/negated SINGLE fp16 [h][kk=128][t]
// ---------------------------------------------------------------------------
__global__ __launch_bounds__(256) void kprep(const float* __restrict__ in,
                                             __half* __restrict__ oh)
{
    __shared__ float st[32][133];
    const int tid = threadIdx.x;
    const int h = blockIdx.x >> 6;
    const int t0 = (blockIdx.x & 63) * 32;
#pragma unroll
    for (int k = 0; k < 4; k++) {
        int i4 = tid + k * 256;
        int t = i4 >> 5, c4 = (i4 & 31) * 4;
        int b = c4 >> 6;
        float4 v = *(const float4*)&in[(size_t)(b * SQ + t0 + t) * DM + h * 64 + (c4 & 63)];
        if (b) { v.x = -v.x; v.y = -v.y; v.z = -v.z; v.w = -v.w; }
        st[t][c4] = v.x; st[t][c4 + 1] = v.y; st[t][c4 + 2] = v.z; st[t][c4 + 3] = v.w;
    }
    __syncthreads();
    const int kk = tid >> 1;
    const int th = (tid & 1) * 16;
    __half hv[16];
#pragma unroll
    for (int j = 0; j < 16; j++)
        hv[j] = __float2half_rn(st[th + j][kk]);
    size_t o = ((size_t)h * 128 + kk) * SQ + t0 + th;
    *(uint4*)&oh[o]     = *(uint4*)&hv[0];
    *(uint4*)&oh[o + 8] = *(uint4*)&hv[8];
}

// ---------------------------------------------------------------------------
// Prep: V1 column sums from fp16 V: o[h][c] = sum_t vh[h][t][64+c]
// ---------------------------------------------------------------------------
__global__ __launch_bounds__(256) void v1sum(const __half* __restrict__ vh,
                                             float* __restrict__ o)
{
    __shared__ float red[4][64];
    int h = blockIdx.x;
    int c = threadIdx.x & 63, q = threadIdx.x >> 6;
    float s = 0.f;
    for (int t = q * 512; t < (q + 1) * 512; t++)
        s += __half2float(vh[((size_t)h * SQ + t) * 128 + 64 + c]);
    red[q][c] = s;
    __syncthreads();
    if (threadIdx.x < 64)
        o[h * 64 + threadIdx.x] = red[0][threadIdx.x] + red[1][threadIdx.x]
                                + red[2][threadIdx.x] + red[3][threadIdx.x];
}

// ---------------------------------------------------------------------------
// fp16 fused attention: Q split hi/lo, K single, V single, 2-term mma.
// smem (fp16 elems):
//   QL 0      [64][136]
//   KH 8704   [128][72]
//   VH 17920  [64][136]  (Q-hi staging at prologue)
//   PH 26624  [64][72]
//   PL 31232  [64][72]
// ---------------------------------------------------------------------------
#define O_QL  0
#define O_KH  8704
#define O_VH  17920
#define O_PH  26624
#define O_PL  31232
#define ATTN_SMEM (35840 * 2)

__global__ void __launch_bounds__(256, 2) attn_tc(
    const __half* __restrict__ qh_g, const __half* __restrict__ ql_g,
    const __half* __restrict__ kth,  const __half* __restrict__ vh_g,
    const float* __restrict__ v1s,
    __half* __restrict__ aoh, __half* __restrict__ aol)
{
    extern __shared__ __half sm[];
    const uint32_t sb = s2u(sm);
    const int tid = threadIdx.x;
    const int wid = tid >> 5, lane = tid & 31;
    const int s0 = blockIdx.x * 64;
    const int h  = blockIdx.y;

    const int wm  = (wid & 3) * 16;
    const int wnt = (wid >> 2) * 32;
    const int wnc = (wid >> 2) * 64;

    const uint32_t aQl = sb + O_QL * 2 + ((wm + (lane & 15)) * 136 + (lane >> 4) * 8) * 2;
    const uint32_t bKh = sb + O_KH * 2 + ((lane & 15) * 72 + wnt + (lane >> 4) * 8) * 2;
    const uint32_t aPh = sb + O_PH * 2 + ((wm + (lane & 15)) * 72 + (lane >> 4) * 8) * 2;
    const uint32_t aPl = sb + O_PL * 2 + ((wm + (lane & 15)) * 72 + (lane >> 4) * 8) * 2;
    const uint32_t bVh = sb + O_VH * 2 + ((lane & 15) * 136 + wnc + (lane >> 4) * 8) * 2;

    // group 0: Q-hi -> VH staging, Q-lo -> QL (2048 chunks)
#pragma unroll
    for (int k = 0; k < 8; k++) {
        int c = tid + k * 256;
        int arr = c >> 10, rem = c & 1023;
        int r = rem >> 4, j = rem & 15;
        const __half* src = (arr ? ql_g : qh_g)
            + ((size_t)h * SQ + s0 + r) * 128 + j * 8;
        uint32_t dst = sb + (arr ? O_QL : O_VH) * 2 + (uint32_t)(r * 136 + j * 8) * 2;
        cpa16(dst, src);
    }
    cpcommit();
    // group 1: K(0) single (1024 chunks: 128 rows x 8)
#pragma unroll
    for (int k = 0; k < 4; k++) {
        int c = tid + k * 256;
        int kk = c >> 3, j = c & 7;
        const __half* src = kth + ((size_t)h * 128 + kk) * SQ + j * 8;
        uint32_t dst = sb + O_KH * 2 + (uint32_t)(kk * 72 + j * 8) * 2;
        cpa16(dst, src);
    }
    cpcommit();
    cpwait1();
    __syncthreads();

    uint32_t qhf[8][4];
    {
        uint32_t aQh = sb + O_VH * 2 + ((wm + (lane & 15)) * 136 + (lane >> 4) * 8) * 2;
#pragma unroll
        for (int ks = 0; ks < 8; ks++)
            ldsm4(qhf[ks], aQh + (uint32_t)(ks * 16) * 2);
    }
    __syncthreads();

    // group 2: V(0) single (1024 chunks: 64 rows x 16)
#pragma unroll
    for (int k = 0; k < 4; k++) {
        int c = tid + k * 256;
        int r = c >> 4, j = c & 15;
        const __half* src = vh_g + ((size_t)h * SQ + r) * 128 + j * 8;
        uint32_t dst = sb + O_VH * 2 + (uint32_t)(r * 136 + j * 8) * 2;
        cpa16(dst, src);
    }
    cpcommit();

    float acc[8][4];
#pragma unroll
    for (int f = 0; f < 8; f++)
#pragma unroll
        for (int j = 0; j < 4; j++) acc[f][j] = 0.f;

    for (int t0 = 0; t0 < SQ; t0 += 64) {
        cpwait1();       // K(i) landed
        __syncthreads();

        // ---- score: Qh(reg)*K + Ql*K ----
        float sc[4][4];
#pragma unroll
        for (int g = 0; g < 4; g++)
#pragma unroll
            for (int j = 0; j < 4; j++) sc[g][j] = 0.f;
#pragma unroll
        for (int ks = 0; ks < 8; ks++) {
            uint32_t ql4[4], kh[2][4];
            ldsm4(ql4, aQl + (uint32_t)(ks * 16) * 2);
#pragma unroll
            for (int p = 0; p < 2; p++)
                ldsm4t(kh[p], bKh + (uint32_t)(ks * 16 * 72 + p * 16) * 2);
#pragma unroll
            for (int p = 0; p < 2; p++) {
                mma16816(sc[2 * p],     qhf[ks], &kh[p][0]);
                mma16816(sc[2 * p + 1], qhf[ks], &kh[p][2]);
                mma16816(sc[2 * p],     ql4,     &kh[p][0]);
                mma16816(sc[2 * p + 1], ql4,     &kh[p][2]);
            }
        }

        // ---- sigmoid + split P ----
        {
            int r0 = wm + (lane >> 2);
            int cb = wnt + (lane & 3) * 2;
#pragma unroll
            for (int g = 0; g < 4; g++) {
                float p0 = 1.f / (1.f + __expf(-0.125f * sc[g][0]));
                float p1 = 1.f / (1.f + __expf(-0.125f * sc[g][1]));
                float p2 = 1.f / (1.f + __expf(-0.125f * sc[g][2]));
                float p3 = 1.f / (1.f + __expf(-0.125f * sc[g][3]));
                uint32_t lo, hi;
                int i0 = r0 * 72 + cb + 8 * g;
                int i1 = (r0 + 8) * 72 + cb + 8 * g;
                hi = packsplit2(p0, p1, lo);
                *(uint32_t*)&sm[O_PH + i0] = hi;  *(uint32_t*)&sm[O_PL + i0] = lo;
                hi = packsplit2(p2, p3, lo);
                *(uint32_t*)&sm[O_PH + i1] = hi;  *(uint32_t*)&sm[O_PL + i1] = lo;
            }
        }
        __syncthreads();

        // prefetch K(i+1)
        if (t0 + 64 < SQ) {
#pragma unroll
            for (int k = 0; k < 4; k++) {
                int c = tid + k * 256;
                int kk = c >> 3, j = c & 7;
                const __half* src = kth + ((size_t)h * 128 + kk) * SQ + (t0 + 64) + j * 8;
                uint32_t dst = sb + O_KH * 2 + (uint32_t)(kk * 72 + j * 8) * 2;
                cpa16(dst, src);
            }
        }
        cpcommit();

        cpwait1();       // V(i) landed
        __syncthreads();

        // ---- PV: Ph*V + Pl*V ----
#pragma unroll
        for (int ks = 0; ks < 4; ks++) {
            uint32_t ph4[4], pl4[4], vh4[4][4];
            ldsm4(ph4, aPh + (uint32_t)(ks * 16) * 2);
            ldsm4(pl4, aPl + (uint32_t)(ks * 16) * 2);
#pragma unroll
            for (int p = 0; p < 4; p++)
                ldsm4t(vh4[p], bVh + (uint32_t)(ks * 16 * 136 + p * 16) * 2);
#pragma unroll
            for (int p = 0; p < 4; p++) {
                mma16816(acc[2 * p],     ph4, &vh4[p][0]);
                mma16816(acc[2 * p + 1], ph4, &vh4[p][2]);
                mma16816(acc[2 * p],     pl4, &vh4[p][0]);
                mma16816(acc[2 * p + 1], pl4, &vh4[p][2]);
            }
        }
        __syncthreads();

        // prefetch V(i+1)
        if (t0 + 64 < SQ) {
#pragma unroll
            for (int k = 0; k < 4; k++) {
                int c = tid + k * 256;
                int r = c >> 4, j = c & 15;
                const __half* src = vh_g + ((size_t)h * SQ + (t0 + 64) + r) * 128 + j * 8;
                uint32_t dst = sb + O_VH * 2 + (uint32_t)(r * 136 + j * 8) * 2;
                cpa16(dst, src);
            }
        }
        cpcommit();
    }
    cpwait0();

    // epilogue: split-write for final GEMM (b=1 uses V1sum - acc)
    {
        int r0 = s0 + wm + (lane >> 2);
#pragma unroll
        for (int f = 0; f < 8; f++) {
            int c = wnc + 8 * f + (lane & 3) * 2;
            int b = c >> 6;
            size_t o = ((size_t)b * SQ + r0) * DM + h * 64 + (c & 63);
            float v00, v01, v10, v11;
            if (b) {
                float sA = v1s[h * 64 + (c & 63)];
                float sB = v1s[h * 64 + (c & 63) + 1];
                v00 = sA - acc[f][0]; v01 = sB - acc[f][1];
                v10 = sA - acc[f][2]; v11 = sB - acc[f][3];
            } else {
                v00 = acc[f][0]; v01 = acc[f][1];
                v10 = acc[f][2]; v11 = acc[f][3];
            }
            uint32_t lo, hi;
            hi = packsplit2(v00, v01, lo);
            *(uint32_t*)&aoh[o] = hi; *(uint32_t*)&aol[o] = lo;
            hi = packsplit2(v10, v11, lo);
            *(uint32_t*)&aoh[o + 8 * DM] = hi; *(uint32_t*)&aol[o + 8 * DM] = lo;
        }
    }
}

// ---------------------------------------------------------------------------
extern "C" void kernel_launch(void* const* d_in, const int* in_sizes, int n_in,
                              void* d_out, int out_size)
{
    const float* query = (const float*)d_in[0];
    const float* key   = (const float*)d_in[1];
    const float* value = (const float*)d_in[2];
    const float* Wq = (const float*)d_in[3];
    const float* bq = (const float*)d_in[4];
    const float* Wk = (const float*)d_in[5];
    const float* bk = (const float*)d_in[6];
    const float* Wv = (const float*)d_in[7];
    const float* bv = (const float*)d_in[8];
    const float* Wo = (const float*)d_in[9];
    const float* bo = (const float*)d_in[10];
    float* out = (float*)d_out;

    float *kp, *v1sp;
    cudaGetSymbolAddress((void**)&kp,   g_k);
    cudaGetSymbolAddress((void**)&v1sp, g_v1s);
    __half *qAh,*qAl,*kAh,*kAl,*vAh,*vAl, *wq,*wk,*wv,*wo;
    __half *qhp,*qlp,*vhp,*vdp,*kthp,*aohp,*aolp;
    cudaGetSymbolAddress((void**)&qAh, g_qAh); cudaGetSymbolAddress((void**)&qAl, g_qAl);
    cudaGetSymbolAddress((void**)&kAh, g_kAh); cudaGetSymbolAddress((void**)&kAl, g_kAl);
    cudaGetSymbolAddress((void**)&vAh, g_vAh); cudaGetSymbolAddress((void**)&vAl, g_vAl);
    cudaGetSymbolAddress((void**)&wq, g_wq);   cudaGetSymbolAddress((void**)&wk, g_wk);
    cudaGetSymbolAddress((void**)&wv, g_wv);   cudaGetSymbolAddress((void**)&wo, g_wo);
    cudaGetSymbolAddress((void**)&qhp, g_qh);  cudaGetSymbolAddress((void**)&qlp, g_ql);
    cudaGetSymbolAddress((void**)&vhp, g_vh);  cudaGetSymbolAddress((void**)&vdp, g_vdummy);
    cudaGetSymbolAddress((void**)&kthp, g_kth);
    cudaGetSymbolAddress((void**)&aohp, g_aoh); cudaGetSymbolAddress((void**)&aolp, g_aol);

    cudaFuncSetAttribute(attn_tc, cudaFuncAttributeMaxDynamicSharedMemorySize,
                         ATTN_SMEM);
    cudaFuncSetAttribute(gemm_hf<0>, cudaFuncAttributeMaxDynamicSharedMemorySize,
                         GEMM_SMEM);
    cudaFuncSetAttribute(gemm_hf<1>, cudaFuncAttributeMaxDynamicSharedMemorySize,
                         GEMM_SMEM);

    dim3 blk(256);
    dim3 gg(DM / 128, MR / 128);

    splitA<<<MR, blk>>>((const float4*)query, qAh, qAl);
    splitA<<<MR, blk>>>((const float4*)key,   kAh, kAl);
    splitA<<<MR, blk>>>((const float4*)value, vAh, vAl);
    roundW1<<<DM, blk>>>(Wq, wq);
    roundW1<<<DM, blk>>>(Wk, wk);
    roundW1<<<DM, blk>>>(Wv, wv);
    roundA<<<DM, blk>>>((const float4*)Wo, wo);

    gemm_hf<1><<<gg, blk, GEMM_SMEM>>>(qAh, qAl, wq, bq, nullptr, qhp, qlp);
    gemm_hf<0><<<gg, blk, GEMM_SMEM>>>(kAh, kAl, wk, bk, kp, nullptr, nullptr);
    gemm_hf<1><<<gg, blk, GEMM_SMEM>>>(vAh, vAl, wv, bv, nullptr, vhp, vdp);

    kprep<<<1024, blk>>>(kp, kthp);
    v1sum<<<NH, blk>>>(vhp, v1sp);

    attn_tc<<<dim3(SQ / 64, NH), blk, ATTN_SMEM>>>(qhp, qlp, kthp, vhp,
                                                   v1sp, aohp, aolp);

    gemm_hf<0><<<gg, blk, GEMM_SMEM>>>(aohp, aolp, wo, bo, out, nullptr, nullptr);
}